// round 5
// baseline (speedup 1.0000x reference)
#include <cuda_runtime.h>

#define BATCH 4
#define SEQ   4096
#define EDIM  256
#define NTOK  (BATCH*SEQ)

// Scratch (device globals: no allocation allowed in kernel_launch)
__device__ float g_Q[NTOK*EDIM];
__device__ float g_K[NTOK*EDIM];
__device__ float g_V[NTOK*EDIM];
__device__ float g_O[NTOK*EDIM];

// ---------------------------------------------------------------------------
// tf32 helpers
// ---------------------------------------------------------------------------
__device__ __forceinline__ unsigned f2tf(float x) {
    unsigned r;
    asm("cvt.rna.tf32.f32 %0, %1;" : "=r"(r) : "f"(x));
    return r;
}

__device__ __forceinline__ void mma_tf32(float* c,
                                         unsigned a0, unsigned a1, unsigned a2, unsigned a3,
                                         unsigned b0, unsigned b1) {
    asm volatile(
        "mma.sync.aligned.m16n8k8.row.col.f32.tf32.tf32.f32 "
        "{%0,%1,%2,%3}, {%4,%5,%6,%7}, {%8,%9}, {%0,%1,%2,%3};"
        : "+f"(c[0]), "+f"(c[1]), "+f"(c[2]), "+f"(c[3])
        : "r"(a0), "r"(a1), "r"(a2), "r"(a3), "r"(b0), "r"(b1));
}

// ---------------------------------------------------------------------------
// Fused QKV projection (unchanged): Y[m,n] = sum_k X[m,k]*W[n,k] + b[n]
// ---------------------------------------------------------------------------
__global__ __launch_bounds__(256) void proj_kernel(
    const float* __restrict__ X,
    const float* __restrict__ Wq, const float* __restrict__ bq,
    const float* __restrict__ Wk, const float* __restrict__ bk,
    const float* __restrict__ Wv, const float* __restrict__ bv)
{
    __shared__ __align__(16) float Xt[32*68];
    __shared__ __align__(16) float Wt[32*68];

    const int mt    = blockIdx.x;
    const int nt    = blockIdx.y;
    const int which = nt >> 2;
    const int n0    = (nt & 3) << 6;
    const int m0    = mt << 6;

    const float* W    = (which == 0) ? Wq : (which == 1) ? Wk : Wv;
    const float* bias = (which == 0) ? bq : (which == 1) ? bk : bv;
    float*       Y    = (which == 0) ? g_Q : (which == 1) ? g_K : g_V;

    const int tid = threadIdx.x;
    const int tx  = tid & 15;
    const int ty  = tid >> 4;

    float acc[4][4] = {};

    for (int kk = 0; kk < EDIM; kk += 32) {
        __syncthreads();
        #pragma unroll
        for (int e = 0; e < 8; e++) {
            int idx = tid + e*256;
            int m = idx >> 5;
            int k = idx & 31;
            Xt[k*68 + m] = X[(m0+m)*EDIM + kk + k];
            Wt[k*68 + m] = W[(n0+m)*EDIM + kk + k];
        }
        __syncthreads();
        #pragma unroll 8
        for (int k = 0; k < 32; k++) {
            float4 a4 = *(const float4*)(Xt + k*68 + 4*ty);
            float4 b4 = *(const float4*)(Wt + k*68 + 4*tx);
            float a[4] = {a4.x, a4.y, a4.z, a4.w};
            float b[4] = {b4.x, b4.y, b4.z, b4.w};
            #pragma unroll
            for (int i = 0; i < 4; i++)
                #pragma unroll
                for (int j = 0; j < 4; j++)
                    acc[i][j] = fmaf(a[i], b[j], acc[i][j]);
        }
    }

    float4 bv4 = *(const float4*)(bias + n0 + 4*tx);
    float bb[4] = {bv4.x, bv4.y, bv4.z, bv4.w};
    #pragma unroll
    for (int i = 0; i < 4; i++) {
        float4 o;
        o.x = acc[i][0] + bb[0];
        o.y = acc[i][1] + bb[1];
        o.z = acc[i][2] + bb[2];
        o.w = acc[i][3] + bb[3];
        *(float4*)(Y + (m0 + 4*ty + i)*EDIM + n0 + 4*tx) = o;
    }
}

// ---------------------------------------------------------------------------
// tf32 mma.sync flash attention + fused residual/LayerNorm.
// CTA: 64 queries, 16 warps (512 threads), key tiles of 64.
//
// Smem (dynamic, float units) — same layout as R3:
//   Qs  [64][260]  tf32 Q tile, row-major
//   Kt  [64][73]   tf32 K chunk, k-major
//   Vs  [64][264]  tf32 V tile, key-major
//   Ss  [64][68]   S / P tile
//   rm/rl/ra [64]  online-softmax state
// ---------------------------------------------------------------------------
#define QS_OFF 0
#define QS_STR 260
#define KT_OFF 16640
#define KT_STR 73
#define VS_OFF 21312
#define VS_STR 264
#define SS_OFF 38208
#define SS_STR 68
#define RM_OFF 42560
#define RL_OFF 42624
#define RA_OFF 42688
#define SMEM_FLOATS 42752   // 171008 bytes

__global__ __launch_bounds__(512, 1) void flash_kernel(
    const float* __restrict__ RES,
    const float* __restrict__ gamma, const float* __restrict__ beta,
    float* __restrict__ OUT)
{
    extern __shared__ float sm[];
    unsigned* QsU = (unsigned*)(sm + QS_OFF);
    unsigned* KtU = (unsigned*)(sm + KT_OFF);
    unsigned* VsU = (unsigned*)(sm + VS_OFF);
    float*    Ss  = sm + SS_OFF;
    float*    rm  = sm + RM_OFF;
    float*    rl  = sm + RL_OFF;
    float*    ra  = sm + RA_OFF;

    const int tid  = threadIdx.x;
    const int warp = tid >> 5;
    const int lane = tid & 31;
    const int ly   = lane >> 2;   // fragment row group
    const int lx   = lane & 3;    // fragment col group

    const int q0   = blockIdx.x << 6;
    const int base = blockIdx.y * SEQ * EDIM;
    const float* Qb = g_Q + base;
    const float* Kb = g_K + base;
    const float* Vb = g_V + base;

    // Phase-A warp tile: rows r0a..+15, keys n0a..+15 (2 n-blocks)
    const int r0a = (warp & 3) << 4;
    const int n0a = (warp >> 2) << 4;
    // Phase-C warp tile: rows r0c..+15, dims d0c..+63 (8 n-blocks)
    const int r0c = (warp & 3) << 4;
    const int d0c = (warp >> 2) << 6;

    // ---- Load Q tile [64 x 256] row-major, tf32-converted, coalesced ----
    #pragma unroll
    for (int i = 0; i < 8; i++) {
        int idx = tid + i*512;          // float4 index
        int row = idx >> 6;
        int c4  = (idx & 63) << 2;
        float4 q = *(const float4*)(Qb + (q0 + row)*EDIM + c4);
        unsigned* dst = QsU + row*QS_STR + c4;
        dst[0] = f2tf(q.x); dst[1] = f2tf(q.y);
        dst[2] = f2tf(q.z); dst[3] = f2tf(q.w);
    }
    if (tid < 64) { rm[tid] = -1e30f; rl[tid] = 0.0f; }

    float acc[8][4];
    #pragma unroll
    for (int nb = 0; nb < 8; nb++)
        #pragma unroll
        for (int r = 0; r < 4; r++) acc[nb][r] = 0.0f;

    for (int kt = 0; kt < 64; kt++) {
        const int key0 = kt << 6;

        // ================= Phase A: S = Q . K^T (tf32 mma) =================
        float sC[2][4];
        #pragma unroll
        for (int nb = 0; nb < 2; nb++)
            #pragma unroll
            for (int r = 0; r < 4; r++) sC[nb][r] = 0.0f;

        for (int kc = 0; kc < 4; kc++) {
            __syncthreads();   // prior readers of Kt/Vs done
            // K chunk: Kt[k][key] = K[key0+key][kc*64+k], k in [0,64)
            #pragma unroll
            for (int i = 0; i < 2; i++) {
                int idx = tid + i*512;          // float4 units: 64 keys x 16
                int key = idx >> 4;
                int g   = (idx & 15) << 2;
                float4 kv = *(const float4*)(Kb + (key0 + key)*EDIM + (kc<<6) + g);
                KtU[(g+0)*KT_STR + key] = f2tf(kv.x);
                KtU[(g+1)*KT_STR + key] = f2tf(kv.y);
                KtU[(g+2)*KT_STR + key] = f2tf(kv.z);
                KtU[(g+3)*KT_STR + key] = f2tf(kv.w);
            }
            // V rows 16*kc..+15 (spread across the 4 chunks)
            #pragma unroll
            for (int i = 0; i < 2; i++) {
                int idx  = tid + i*512;         // float4 units: 16 rows x 64
                int vrow = (kc << 4) + (idx >> 6);
                int c4   = (idx & 63) << 2;
                float4 vv = *(const float4*)(Vb + (key0 + vrow)*EDIM + c4);
                unsigned* dst = VsU + vrow*VS_STR + c4;
                dst[0] = f2tf(vv.x); dst[1] = f2tf(vv.y);
                dst[2] = f2tf(vv.z); dst[3] = f2tf(vv.w);
            }
            __syncthreads();

            #pragma unroll
            for (int ks = 0; ks < 8; ks++) {
                const int kb = (kc << 6) + (ks << 3);
                unsigned a0 = QsU[(r0a + ly    )*QS_STR + kb + lx    ];
                unsigned a1 = QsU[(r0a + ly + 8)*QS_STR + kb + lx    ];
                unsigned a2 = QsU[(r0a + ly    )*QS_STR + kb + lx + 4];
                unsigned a3 = QsU[(r0a + ly + 8)*QS_STR + kb + lx + 4];
                #pragma unroll
                for (int nb = 0; nb < 2; nb++) {
                    const int n = n0a + (nb << 3) + ly;
                    unsigned b0 = KtU[((ks<<3) + lx    )*KT_STR + n];
                    unsigned b1 = KtU[((ks<<3) + lx + 4)*KT_STR + n];
                    mma_tf32(sC[nb], a0, a1, a2, a3, b0, b1);
                }
            }
        }

        // store scaled scores to Ss (scale = 1/sqrt(4096) = 1/64)
        {
            const float scale = 0.015625f;
            #pragma unroll
            for (int nb = 0; nb < 2; nb++) {
                const int col = n0a + (nb << 3) + (lx << 1);
                *(float2*)(Ss + (r0a + ly    )*SS_STR + col) =
                    make_float2(sC[nb][0]*scale, sC[nb][1]*scale);
                *(float2*)(Ss + (r0a + ly + 8)*SS_STR + col) =
                    make_float2(sC[nb][2]*scale, sC[nb][3]*scale);
            }
        }
        __syncthreads();

        // ================= Phase B: online softmax (8 threads/row) ==========
        {
            const int row = tid >> 3;
            const int qq  = tid & 7;
            float* srow = Ss + row*SS_STR + (qq << 3);
            float4 v0 = *(float4*)(srow + 0);
            float4 v1 = *(float4*)(srow + 4);
            float mo = rm[row];
            float mx = fmaxf(fmaxf(fmaxf(v0.x, v0.y), fmaxf(v0.z, v0.w)),
                             fmaxf(fmaxf(v1.x, v1.y), fmaxf(v1.z, v1.w)));
            mx = fmaxf(mx, __shfl_xor_sync(0xffffffffu, mx, 1));
            mx = fmaxf(mx, __shfl_xor_sync(0xffffffffu, mx, 2));
            mx = fmaxf(mx, __shfl_xor_sync(0xffffffffu, mx, 4));
            mx = fmaxf(mx, mo);
            v0.x = __expf(v0.x - mx); v0.y = __expf(v0.y - mx);
            v0.z = __expf(v0.z - mx); v0.w = __expf(v0.w - mx);
            v1.x = __expf(v1.x - mx); v1.y = __expf(v1.y - mx);
            v1.z = __expf(v1.z - mx); v1.w = __expf(v1.w - mx);
            float s = v0.x+v0.y+v0.z+v0.w + v1.x+v1.y+v1.z+v1.w;
            s += __shfl_xor_sync(0xffffffffu, s, 1);
            s += __shfl_xor_sync(0xffffffffu, s, 2);
            s += __shfl_xor_sync(0xffffffffu, s, 4);
            *(float4*)(srow + 0) = v0;
            *(float4*)(srow + 4) = v1;
            if (qq == 0) {
                float alpha = __expf(mo - mx);
                rm[row] = mx;
                rl[row] = rl[row]*alpha + s;
                ra[row] = alpha;
            }
        }
        __syncthreads();

        // ================= Phase C: O += P . V (tf32 mma) ===================
        {
            float al0 = ra[r0c + ly];
            float al1 = ra[r0c + ly + 8];
            #pragma unroll
            for (int nb = 0; nb < 8; nb++) {
                acc[nb][0] *= al0; acc[nb][1] *= al0;
                acc[nb][2] *= al1; acc[nb][3] *= al1;
            }
        }
        const unsigned* SsU = (const unsigned*)Ss;
        #pragma unroll
        for (int ks = 0; ks < 8; ks++) {
            unsigned a0 = SsU[(r0c + ly    )*SS_STR + (ks<<3) + lx    ];
            unsigned a1 = SsU[(r0c + ly + 8)*SS_STR + (ks<<3) + lx    ];
            unsigned a2 = SsU[(r0c + ly    )*SS_STR + (ks<<3) + lx + 4];
            unsigned a3 = SsU[(r0c + ly + 8)*SS_STR + (ks<<3) + lx + 4];
            #pragma unroll
            for (int nb = 0; nb < 8; nb++) {
                const int n = d0c + (nb << 3) + ly;
                unsigned b0 = VsU[((ks<<3) + lx    )*VS_STR + n];
                unsigned b1 = VsU[((ks<<3) + lx + 4)*VS_STR + n];
                mma_tf32(acc[nb], a0, a1, a2, a3, b0, b1);
            }
        }
    }
    __syncthreads();

    // ---- Epilogue: scatter h = acc/rl into Vs, then residual + LayerNorm ----
    float* Vf = sm + VS_OFF;
    {
        float il0 = 1.0f / rl[r0c + ly];
        float il1 = 1.0f / rl[r0c + ly + 8];
        #pragma unroll
        for (int nb = 0; nb < 8; nb++) {
            const int n = d0c + (nb << 3) + (lx << 1);
            *(float2*)(Vf + (r0c + ly    )*VS_STR + n) =
                make_float2(acc[nb][0]*il0, acc[nb][1]*il0);
            *(float2*)(Vf + (r0c + ly + 8)*VS_STR + n) =
                make_float2(acc[nb][2]*il1, acc[nb][3]*il1);
        }
    }
    __syncthreads();

    #pragma unroll
    for (int rr = 0; rr < 4; rr++) {
        const int row = (warp << 2) + rr;
        const int d   = lane << 3;
        float4 h0 = *(float4*)(Vf + row*VS_STR + d);
        float4 h1 = *(float4*)(Vf + row*VS_STR + d + 4);
        const float* resrow = RES + base + (q0 + row)*EDIM + d;
        float4 x0 = *(const float4*)(resrow);
        float4 x1 = *(const float4*)(resrow + 4);
        h0.x += x0.x; h0.y += x0.y; h0.z += x0.z; h0.w += x0.w;
        h1.x += x1.x; h1.y += x1.y; h1.z += x1.z; h1.w += x1.w;
        float s1 = h0.x+h0.y+h0.z+h0.w + h1.x+h1.y+h1.z+h1.w;
        float s2 = h0.x*h0.x + h0.y*h0.y + h0.z*h0.z + h0.w*h0.w
                 + h1.x*h1.x + h1.y*h1.y + h1.z*h1.z + h1.w*h1.w;
        #pragma unroll
        for (int off = 16; off >= 1; off >>= 1) {
            s1 += __shfl_xor_sync(0xffffffffu, s1, off);
            s2 += __shfl_xor_sync(0xffffffffu, s2, off);
        }
        const float mu  = s1 * (1.0f/256.0f);
        const float var = s2 * (1.0f/256.0f) - mu*mu;
        const float rs  = rsqrtf(var + 1e-5f);
        float4 g0 = *(const float4*)(gamma + d);
        float4 g1 = *(const float4*)(gamma + d + 4);
        float4 b0 = *(const float4*)(beta + d);
        float4 b1 = *(const float4*)(beta + d + 4);
        float4 o0, o1;
        o0.x = (h0.x-mu)*rs*g0.x + b0.x;  o0.y = (h0.y-mu)*rs*g0.y + b0.y;
        o0.z = (h0.z-mu)*rs*g0.z + b0.z;  o0.w = (h0.w-mu)*rs*g0.w + b0.w;
        o1.x = (h1.x-mu)*rs*g1.x + b1.x;  o1.y = (h1.y-mu)*rs*g1.y + b1.y;
        o1.z = (h1.z-mu)*rs*g1.z + b1.z;  o1.w = (h1.w-mu)*rs*g1.w + b1.w;
        float* orow = OUT + base + (q0 + row)*EDIM + d;
        *(float4*)(orow)     = o0;
        *(float4*)(orow + 4) = o1;
    }
}

// ---------------------------------------------------------------------------
extern "C" void kernel_launch(void* const* d_in, const int* in_sizes, int n_in,
                              void* d_out, int out_size) {
    const float* x     = (const float*)d_in[0];
    const float* Wq1   = (const float*)d_in[1];
    const float* bq1   = (const float*)d_in[2];
    const float* Wk1   = (const float*)d_in[3];
    const float* bk1   = (const float*)d_in[4];
    const float* Wv1   = (const float*)d_in[5];
    const float* bv1   = (const float*)d_in[6];
    const float* Wq2   = (const float*)d_in[7];
    const float* bq2   = (const float*)d_in[8];
    const float* Wk2   = (const float*)d_in[9];
    const float* bk2   = (const float*)d_in[10];
    const float* Wv2   = (const float*)d_in[11];
    const float* bv2   = (const float*)d_in[12];
    const float* g1    = (const float*)d_in[13];
    const float* beta1 = (const float*)d_in[14];
    const float* g2    = (const float*)d_in[15];
    const float* beta2 = (const float*)d_in[16];
    float* out = (float*)d_out;

    float* O = nullptr;
    cudaGetSymbolAddress((void**)&O, g_O);

    const size_t smem = (size_t)SMEM_FLOATS * sizeof(float); // 171008 B
    cudaFuncSetAttribute(flash_kernel, cudaFuncAttributeMaxDynamicSharedMemorySize, (int)smem);

    dim3 pg(NTOK/64, 12), pb(256);
    dim3 fg(SEQ/64, BATCH), fb(512);

    // Layer 1
    proj_kernel<<<pg, pb>>>(x, Wq1, bq1, Wk1, bk1, Wv1, bv1);
    flash_kernel<<<fg, fb, smem>>>(x, g1, beta1, O);
    // Layer 2
    proj_kernel<<<pg, pb>>>(O, Wq2, bq2, Wk2, bk2, Wv2, bv2);
    flash_kernel<<<fg, fb, smem>>>(O, g2, beta2, out);
}

// round 6
// speedup vs baseline: 1.0001x; 1.0001x over previous
#include <cuda_runtime.h>

#define BATCH 4
#define SEQ   4096
#define EDIM  256
#define NTOK  (BATCH*SEQ)

// Scratch (device globals: no allocation allowed in kernel_launch)
__device__ float g_Q[NTOK*EDIM];
__device__ float g_K[NTOK*EDIM];
__device__ float g_V[NTOK*EDIM];
__device__ float g_O[NTOK*EDIM];

// ---------------------------------------------------------------------------
// tf32 helpers
// ---------------------------------------------------------------------------
__device__ __forceinline__ unsigned f2tf(float x) {
    unsigned r;
    asm("cvt.rna.tf32.f32 %0, %1;" : "=r"(r) : "f"(x));
    return r;
}

__device__ __forceinline__ void mma_tf32(float* c,
                                         unsigned a0, unsigned a1, unsigned a2, unsigned a3,
                                         unsigned b0, unsigned b1) {
    asm volatile(
        "mma.sync.aligned.m16n8k8.row.col.f32.tf32.tf32.f32 "
        "{%0,%1,%2,%3}, {%4,%5,%6,%7}, {%8,%9}, {%0,%1,%2,%3};"
        : "+f"(c[0]), "+f"(c[1]), "+f"(c[2]), "+f"(c[3])
        : "r"(a0), "r"(a1), "r"(a2), "r"(a3), "r"(b0), "r"(b1));
}

// ---------------------------------------------------------------------------
// Fused QKV projection (unchanged): Y[m,n] = sum_k X[m,k]*W[n,k] + b[n]
// ---------------------------------------------------------------------------
__global__ __launch_bounds__(256) void proj_kernel(
    const float* __restrict__ X,
    const float* __restrict__ Wq, const float* __restrict__ bq,
    const float* __restrict__ Wk, const float* __restrict__ bk,
    const float* __restrict__ Wv, const float* __restrict__ bv)
{
    __shared__ __align__(16) float Xt[32*68];
    __shared__ __align__(16) float Wt[32*68];

    const int mt    = blockIdx.x;
    const int nt    = blockIdx.y;
    const int which = nt >> 2;
    const int n0    = (nt & 3) << 6;
    const int m0    = mt << 6;

    const float* W    = (which == 0) ? Wq : (which == 1) ? Wk : Wv;
    const float* bias = (which == 0) ? bq : (which == 1) ? bk : bv;
    float*       Y    = (which == 0) ? g_Q : (which == 1) ? g_K : g_V;

    const int tid = threadIdx.x;
    const int tx  = tid & 15;
    const int ty  = tid >> 4;

    float acc[4][4] = {};

    for (int kk = 0; kk < EDIM; kk += 32) {
        __syncthreads();
        #pragma unroll
        for (int e = 0; e < 8; e++) {
            int idx = tid + e*256;
            int m = idx >> 5;
            int k = idx & 31;
            Xt[k*68 + m] = X[(m0+m)*EDIM + kk + k];
            Wt[k*68 + m] = W[(n0+m)*EDIM + kk + k];
        }
        __syncthreads();
        #pragma unroll 8
        for (int k = 0; k < 32; k++) {
            float4 a4 = *(const float4*)(Xt + k*68 + 4*ty);
            float4 b4 = *(const float4*)(Wt + k*68 + 4*tx);
            float a[4] = {a4.x, a4.y, a4.z, a4.w};
            float b[4] = {b4.x, b4.y, b4.z, b4.w};
            #pragma unroll
            for (int i = 0; i < 4; i++)
                #pragma unroll
                for (int j = 0; j < 4; j++)
                    acc[i][j] = fmaf(a[i], b[j], acc[i][j]);
        }
    }

    float4 bv4 = *(const float4*)(bias + n0 + 4*tx);
    float bb[4] = {bv4.x, bv4.y, bv4.z, bv4.w};
    #pragma unroll
    for (int i = 0; i < 4; i++) {
        float4 o;
        o.x = acc[i][0] + bb[0];
        o.y = acc[i][1] + bb[1];
        o.z = acc[i][2] + bb[2];
        o.w = acc[i][3] + bb[3];
        *(float4*)(Y + (m0 + 4*ty + i)*EDIM + n0 + 4*tx) = o;
    }
}

// ---------------------------------------------------------------------------
// tf32 mma.sync flash attention + fused residual/LayerNorm.
// CTA: 64 queries, 16 warps (512 threads), key tiles of 64.
//
// Smem (dynamic, float units) — same layout as R3:
//   Qs  [64][260]  tf32 Q tile, row-major
//   Kt  [64][73]   tf32 K chunk, k-major
//   Vs  [64][264]  tf32 V tile, key-major
//   Ss  [64][68]   S / P tile
//   rm/rl/ra [64]  online-softmax state
// ---------------------------------------------------------------------------
#define QS_OFF 0
#define QS_STR 260
#define KT_OFF 16640
#define KT_STR 73
#define VS_OFF 21312
#define VS_STR 264
#define SS_OFF 38208
#define SS_STR 68
#define RM_OFF 42560
#define RL_OFF 42624
#define RA_OFF 42688
#define SMEM_FLOATS 42752   // 171008 bytes

__global__ __launch_bounds__(512, 1) void flash_kernel(
    const float* __restrict__ RES,
    const float* __restrict__ gamma, const float* __restrict__ beta,
    float* __restrict__ OUT)
{
    extern __shared__ float sm[];
    unsigned* QsU = (unsigned*)(sm + QS_OFF);
    unsigned* KtU = (unsigned*)(sm + KT_OFF);
    unsigned* VsU = (unsigned*)(sm + VS_OFF);
    float*    Ss  = sm + SS_OFF;
    float*    rm  = sm + RM_OFF;
    float*    rl  = sm + RL_OFF;
    float*    ra  = sm + RA_OFF;

    const int tid  = threadIdx.x;
    const int warp = tid >> 5;
    const int lane = tid & 31;
    const int ly   = lane >> 2;   // fragment row group
    const int lx   = lane & 3;    // fragment col group

    const int q0   = blockIdx.x << 6;
    const int base = blockIdx.y * SEQ * EDIM;
    const float* Qb = g_Q + base;
    const float* Kb = g_K + base;
    const float* Vb = g_V + base;

    // Phase-A warp tile: rows r0a..+15, keys n0a..+15 (2 n-blocks)
    const int r0a = (warp & 3) << 4;
    const int n0a = (warp >> 2) << 4;
    // Phase-C warp tile: rows r0c..+15, dims d0c..+63 (8 n-blocks)
    const int r0c = (warp & 3) << 4;
    const int d0c = (warp >> 2) << 6;

    // ---- Load Q tile [64 x 256] row-major, tf32-converted, coalesced ----
    #pragma unroll
    for (int i = 0; i < 8; i++) {
        int idx = tid + i*512;          // float4 index
        int row = idx >> 6;
        int c4  = (idx & 63) << 2;
        float4 q = *(const float4*)(Qb + (q0 + row)*EDIM + c4);
        unsigned* dst = QsU + row*QS_STR + c4;
        dst[0] = f2tf(q.x); dst[1] = f2tf(q.y);
        dst[2] = f2tf(q.z); dst[3] = f2tf(q.w);
    }
    if (tid < 64) { rm[tid] = -1e30f; rl[tid] = 0.0f; }

    float acc[8][4];
    #pragma unroll
    for (int nb = 0; nb < 8; nb++)
        #pragma unroll
        for (int r = 0; r < 4; r++) acc[nb][r] = 0.0f;

    for (int kt = 0; kt < 64; kt++) {
        const int key0 = kt << 6;

        // ================= Phase A: S = Q . K^T (tf32 mma) =================
        float sC[2][4];
        #pragma unroll
        for (int nb = 0; nb < 2; nb++)
            #pragma unroll
            for (int r = 0; r < 4; r++) sC[nb][r] = 0.0f;

        for (int kc = 0; kc < 4; kc++) {
            __syncthreads();   // prior readers of Kt/Vs done
            // K chunk: Kt[k][key] = K[key0+key][kc*64+k], k in [0,64)
            #pragma unroll
            for (int i = 0; i < 2; i++) {
                int idx = tid + i*512;          // float4 units: 64 keys x 16
                int key = idx >> 4;
                int g   = (idx & 15) << 2;
                float4 kv = *(const float4*)(Kb + (key0 + key)*EDIM + (kc<<6) + g);
                KtU[(g+0)*KT_STR + key] = f2tf(kv.x);
                KtU[(g+1)*KT_STR + key] = f2tf(kv.y);
                KtU[(g+2)*KT_STR + key] = f2tf(kv.z);
                KtU[(g+3)*KT_STR + key] = f2tf(kv.w);
            }
            // V rows 16*kc..+15 (spread across the 4 chunks)
            #pragma unroll
            for (int i = 0; i < 2; i++) {
                int idx  = tid + i*512;         // float4 units: 16 rows x 64
                int vrow = (kc << 4) + (idx >> 6);
                int c4   = (idx & 63) << 2;
                float4 vv = *(const float4*)(Vb + (key0 + vrow)*EDIM + c4);
                unsigned* dst = VsU + vrow*VS_STR + c4;
                dst[0] = f2tf(vv.x); dst[1] = f2tf(vv.y);
                dst[2] = f2tf(vv.z); dst[3] = f2tf(vv.w);
            }
            __syncthreads();

            #pragma unroll
            for (int ks = 0; ks < 8; ks++) {
                const int kb = (kc << 6) + (ks << 3);
                unsigned a0 = QsU[(r0a + ly    )*QS_STR + kb + lx    ];
                unsigned a1 = QsU[(r0a + ly + 8)*QS_STR + kb + lx    ];
                unsigned a2 = QsU[(r0a + ly    )*QS_STR + kb + lx + 4];
                unsigned a3 = QsU[(r0a + ly + 8)*QS_STR + kb + lx + 4];
                #pragma unroll
                for (int nb = 0; nb < 2; nb++) {
                    const int n = n0a + (nb << 3) + ly;
                    unsigned b0 = KtU[((ks<<3) + lx    )*KT_STR + n];
                    unsigned b1 = KtU[((ks<<3) + lx + 4)*KT_STR + n];
                    mma_tf32(sC[nb], a0, a1, a2, a3, b0, b1);
                }
            }
        }

        // store scaled scores to Ss (scale = 1/sqrt(4096) = 1/64)
        {
            const float scale = 0.015625f;
            #pragma unroll
            for (int nb = 0; nb < 2; nb++) {
                const int col = n0a + (nb << 3) + (lx << 1);
                *(float2*)(Ss + (r0a + ly    )*SS_STR + col) =
                    make_float2(sC[nb][0]*scale, sC[nb][1]*scale);
                *(float2*)(Ss + (r0a + ly + 8)*SS_STR + col) =
                    make_float2(sC[nb][2]*scale, sC[nb][3]*scale);
            }
        }
        __syncthreads();

        // ================= Phase B: online softmax (8 threads/row) ==========
        {
            const int row = tid >> 3;
            const int qq  = tid & 7;
            float* srow = Ss + row*SS_STR + (qq << 3);
            float4 v0 = *(float4*)(srow + 0);
            float4 v1 = *(float4*)(srow + 4);
            float mo = rm[row];
            float mx = fmaxf(fmaxf(fmaxf(v0.x, v0.y), fmaxf(v0.z, v0.w)),
                             fmaxf(fmaxf(v1.x, v1.y), fmaxf(v1.z, v1.w)));
            mx = fmaxf(mx, __shfl_xor_sync(0xffffffffu, mx, 1));
            mx = fmaxf(mx, __shfl_xor_sync(0xffffffffu, mx, 2));
            mx = fmaxf(mx, __shfl_xor_sync(0xffffffffu, mx, 4));
            mx = fmaxf(mx, mo);
            v0.x = __expf(v0.x - mx); v0.y = __expf(v0.y - mx);
            v0.z = __expf(v0.z - mx); v0.w = __expf(v0.w - mx);
            v1.x = __expf(v1.x - mx); v1.y = __expf(v1.y - mx);
            v1.z = __expf(v1.z - mx); v1.w = __expf(v1.w - mx);
            float s = v0.x+v0.y+v0.z+v0.w + v1.x+v1.y+v1.z+v1.w;
            s += __shfl_xor_sync(0xffffffffu, s, 1);
            s += __shfl_xor_sync(0xffffffffu, s, 2);
            s += __shfl_xor_sync(0xffffffffu, s, 4);
            *(float4*)(srow + 0) = v0;
            *(float4*)(srow + 4) = v1;
            if (qq == 0) {
                float alpha = __expf(mo - mx);
                rm[row] = mx;
                rl[row] = rl[row]*alpha + s;
                ra[row] = alpha;
            }
        }
        __syncthreads();

        // ================= Phase C: O += P . V (tf32 mma) ===================
        {
            float al0 = ra[r0c + ly];
            float al1 = ra[r0c + ly + 8];
            #pragma unroll
            for (int nb = 0; nb < 8; nb++) {
                acc[nb][0] *= al0; acc[nb][1] *= al0;
                acc[nb][2] *= al1; acc[nb][3] *= al1;
            }
        }
        const unsigned* SsU = (const unsigned*)Ss;
        #pragma unroll
        for (int ks = 0; ks < 8; ks++) {
            unsigned a0 = SsU[(r0c + ly    )*SS_STR + (ks<<3) + lx    ];
            unsigned a1 = SsU[(r0c + ly + 8)*SS_STR + (ks<<3) + lx    ];
            unsigned a2 = SsU[(r0c + ly    )*SS_STR + (ks<<3) + lx + 4];
            unsigned a3 = SsU[(r0c + ly + 8)*SS_STR + (ks<<3) + lx + 4];
            #pragma unroll
            for (int nb = 0; nb < 8; nb++) {
                const int n = d0c + (nb << 3) + ly;
                unsigned b0 = VsU[((ks<<3) + lx    )*VS_STR + n];
                unsigned b1 = VsU[((ks<<3) + lx + 4)*VS_STR + n];
                mma_tf32(acc[nb], a0, a1, a2, a3, b0, b1);
            }
        }
    }
    __syncthreads();

    // ---- Epilogue: scatter h = acc/rl into Vs, then residual + LayerNorm ----
    float* Vf = sm + VS_OFF;
    {
        float il0 = 1.0f / rl[r0c + ly];
        float il1 = 1.0f / rl[r0c + ly + 8];
        #pragma unroll
        for (int nb = 0; nb < 8; nb++) {
            const int n = d0c + (nb << 3) + (lx << 1);
            *(float2*)(Vf + (r0c + ly    )*VS_STR + n) =
                make_float2(acc[nb][0]*il0, acc[nb][1]*il0);
            *(float2*)(Vf + (r0c + ly + 8)*VS_STR + n) =
                make_float2(acc[nb][2]*il1, acc[nb][3]*il1);
        }
    }
    __syncthreads();

    #pragma unroll
    for (int rr = 0; rr < 4; rr++) {
        const int row = (warp << 2) + rr;
        const int d   = lane << 3;
        float4 h0 = *(float4*)(Vf + row*VS_STR + d);
        float4 h1 = *(float4*)(Vf + row*VS_STR + d + 4);
        const float* resrow = RES + base + (q0 + row)*EDIM + d;
        float4 x0 = *(const float4*)(resrow);
        float4 x1 = *(const float4*)(resrow + 4);
        h0.x += x0.x; h0.y += x0.y; h0.z += x0.z; h0.w += x0.w;
        h1.x += x1.x; h1.y += x1.y; h1.z += x1.z; h1.w += x1.w;
        float s1 = h0.x+h0.y+h0.z+h0.w + h1.x+h1.y+h1.z+h1.w;
        float s2 = h0.x*h0.x + h0.y*h0.y + h0.z*h0.z + h0.w*h0.w
                 + h1.x*h1.x + h1.y*h1.y + h1.z*h1.z + h1.w*h1.w;
        #pragma unroll
        for (int off = 16; off >= 1; off >>= 1) {
            s1 += __shfl_xor_sync(0xffffffffu, s1, off);
            s2 += __shfl_xor_sync(0xffffffffu, s2, off);
        }
        const float mu  = s1 * (1.0f/256.0f);
        const float var = s2 * (1.0f/256.0f) - mu*mu;
        const float rs  = rsqrtf(var + 1e-5f);
        float4 g0 = *(const float4*)(gamma + d);
        float4 g1 = *(const float4*)(gamma + d + 4);
        float4 b0 = *(const float4*)(beta + d);
        float4 b1 = *(const float4*)(beta + d + 4);
        float4 o0, o1;
        o0.x = (h0.x-mu)*rs*g0.x + b0.x;  o0.y = (h0.y-mu)*rs*g0.y + b0.y;
        o0.z = (h0.z-mu)*rs*g0.z + b0.z;  o0.w = (h0.w-mu)*rs*g0.w + b0.w;
        o1.x = (h1.x-mu)*rs*g1.x + b1.x;  o1.y = (h1.y-mu)*rs*g1.y + b1.y;
        o1.z = (h1.z-mu)*rs*g1.z + b1.z;  o1.w = (h1.w-mu)*rs*g1.w + b1.w;
        float* orow = OUT + base + (q0 + row)*EDIM + d;
        *(float4*)(orow)     = o0;
        *(float4*)(orow + 4) = o1;
    }
}

// ---------------------------------------------------------------------------
extern "C" void kernel_launch(void* const* d_in, const int* in_sizes, int n_in,
                              void* d_out, int out_size) {
    const float* x     = (const float*)d_in[0];
    const float* Wq1   = (const float*)d_in[1];
    const float* bq1   = (const float*)d_in[2];
    const float* Wk1   = (const float*)d_in[3];
    const float* bk1   = (const float*)d_in[4];
    const float* Wv1   = (const float*)d_in[5];
    const float* bv1   = (const float*)d_in[6];
    const float* Wq2   = (const float*)d_in[7];
    const float* bq2   = (const float*)d_in[8];
    const float* Wk2   = (const float*)d_in[9];
    const float* bk2   = (const float*)d_in[10];
    const float* Wv2   = (const float*)d_in[11];
    const float* bv2   = (const float*)d_in[12];
    const float* g1    = (const float*)d_in[13];
    const float* beta1 = (const float*)d_in[14];
    const float* g2    = (const float*)d_in[15];
    const float* beta2 = (const float*)d_in[16];
    float* out = (float*)d_out;

    float* O = nullptr;
    cudaGetSymbolAddress((void**)&O, g_O);

    const size_t smem = (size_t)SMEM_FLOATS * sizeof(float); // 171008 B
    cudaFuncSetAttribute(flash_kernel, cudaFuncAttributeMaxDynamicSharedMemorySize, (int)smem);

    dim3 pg(NTOK/64, 12), pb(256);
    dim3 fg(SEQ/64, BATCH), fb(512);

    // Layer 1
    proj_kernel<<<pg, pb>>>(x, Wq1, bq1, Wk1, bk1, Wv1, bv1);
    flash_kernel<<<fg, fb, smem>>>(x, g1, beta1, O);
    // Layer 2
    proj_kernel<<<pg, pb>>>(O, Wq2, bq2, Wk2, bk2, Wv2, bv2);
    flash_kernel<<<fg, fb, smem>>>(O, g2, beta2, out);
}

// round 8
// speedup vs baseline: 2.2533x; 2.2532x over previous
#include <cuda_runtime.h>
#include <cuda_bf16.h>
#include <cstdint>

#define BATCH 4
#define SEQ   4096
#define EDIM  256
#define NTOK  (BATCH*SEQ)

// Scratch (device globals: no allocation allowed in kernel_launch)
__device__ __nv_bfloat16 g_Q[NTOK*EDIM];
__device__ __nv_bfloat16 g_K[NTOK*EDIM];
__device__ __nv_bfloat16 g_V[NTOK*EDIM];
__device__ float         g_O[NTOK*EDIM];

// ---------------------------------------------------------------------------
// mma / ldmatrix helpers (bf16 m16n8k16, fp32 accum)
// ---------------------------------------------------------------------------
__device__ __forceinline__ uint32_t smem_u32(const void* p) {
    uint32_t a;
    asm("{ .reg .u64 t; cvta.to.shared.u64 t, %1; cvt.u32.u64 %0, t; }" : "=r"(a) : "l"(p));
    return a;
}

__device__ __forceinline__ void mma_bf16(float* c,
                                         uint32_t a0, uint32_t a1, uint32_t a2, uint32_t a3,
                                         uint32_t b0, uint32_t b1) {
    asm volatile(
        "mma.sync.aligned.m16n8k16.row.col.f32.bf16.bf16.f32 "
        "{%0,%1,%2,%3}, {%4,%5,%6,%7}, {%8,%9}, {%0,%1,%2,%3};"
        : "+f"(c[0]), "+f"(c[1]), "+f"(c[2]), "+f"(c[3])
        : "r"(a0), "r"(a1), "r"(a2), "r"(a3), "r"(b0), "r"(b1));
}

__device__ __forceinline__ void ldsm_x4(uint32_t& r0, uint32_t& r1, uint32_t& r2, uint32_t& r3,
                                        uint32_t addr) {
    asm volatile("ldmatrix.sync.aligned.m8n8.x4.shared.b16 {%0,%1,%2,%3}, [%4];"
                 : "=r"(r0), "=r"(r1), "=r"(r2), "=r"(r3) : "r"(addr));
}

__device__ __forceinline__ void ldsm_x4t(uint32_t& r0, uint32_t& r1, uint32_t& r2, uint32_t& r3,
                                         uint32_t addr) {
    asm volatile("ldmatrix.sync.aligned.m8n8.x4.trans.shared.b16 {%0,%1,%2,%3}, [%4];"
                 : "=r"(r0), "=r"(r1), "=r"(r2), "=r"(r3) : "r"(addr));
}

// ---------------------------------------------------------------------------
// Fused QKV projection (FFMA) — now emits bf16 outputs.
// Y[m,n] = bf16( sum_k X[m,k]*W[n,k] + b[n] )
// ---------------------------------------------------------------------------
__global__ __launch_bounds__(256) void proj_kernel(
    const float* __restrict__ X,
    const float* __restrict__ Wq, const float* __restrict__ bq,
    const float* __restrict__ Wk, const float* __restrict__ bk,
    const float* __restrict__ Wv, const float* __restrict__ bv)
{
    __shared__ __align__(16) float Xt[32*68];
    __shared__ __align__(16) float Wt[32*68];

    const int mt    = blockIdx.x;
    const int nt    = blockIdx.y;
    const int which = nt >> 2;
    const int n0    = (nt & 3) << 6;
    const int m0    = mt << 6;

    const float* W    = (which == 0) ? Wq : (which == 1) ? Wk : Wv;
    const float* bias = (which == 0) ? bq : (which == 1) ? bk : bv;
    __nv_bfloat16* Y  = (which == 0) ? g_Q : (which == 1) ? g_K : g_V;

    const int tid = threadIdx.x;
    const int tx  = tid & 15;
    const int ty  = tid >> 4;

    float acc[4][4] = {};

    for (int kk = 0; kk < EDIM; kk += 32) {
        __syncthreads();
        #pragma unroll
        for (int e = 0; e < 8; e++) {
            int idx = tid + e*256;
            int m = idx >> 5;
            int k = idx & 31;
            Xt[k*68 + m] = X[(m0+m)*EDIM + kk + k];
            Wt[k*68 + m] = W[(n0+m)*EDIM + kk + k];
        }
        __syncthreads();
        #pragma unroll 8
        for (int k = 0; k < 32; k++) {
            float4 a4 = *(const float4*)(Xt + k*68 + 4*ty);
            float4 b4 = *(const float4*)(Wt + k*68 + 4*tx);
            float a[4] = {a4.x, a4.y, a4.z, a4.w};
            float b[4] = {b4.x, b4.y, b4.z, b4.w};
            #pragma unroll
            for (int i = 0; i < 4; i++)
                #pragma unroll
                for (int j = 0; j < 4; j++)
                    acc[i][j] = fmaf(a[i], b[j], acc[i][j]);
        }
    }

    float4 bv4 = *(const float4*)(bias + n0 + 4*tx);
    #pragma unroll
    for (int i = 0; i < 4; i++) {
        __nv_bfloat162 p0 = __floats2bfloat162_rn(acc[i][0] + bv4.x, acc[i][1] + bv4.y);
        __nv_bfloat162 p1 = __floats2bfloat162_rn(acc[i][2] + bv4.z, acc[i][3] + bv4.w);
        uint2 pk;
        pk.x = *(uint32_t*)&p0;
        pk.y = *(uint32_t*)&p1;
        *(uint2*)(Y + (m0 + 4*ty + i)*EDIM + n0 + 4*tx) = pk;
    }
}

// ---------------------------------------------------------------------------
// bf16 mma.sync flash attention + fused residual/LayerNorm.
// CTA: 64 queries, 8 warps (256 threads), key tiles of 64, K chunked by 64.
//
// Smem (dynamic, bytes):
//   Qs bf16 [64][264]  @0       (33792)  A-frags, stride 264h = 132w == 4 mod 32
//   Ks bf16 [64][72]   @33792   (9216)   B-frags (K chunk, k-major rows)
//   Vs bf16 [64][264]  @43008   (33792)  B-frags via ldmatrix.trans (row-major)
//   Ss f32  [64][68]   @76800   (17408)  raw scores
//   Ps bf16 [64][72]   @94208   (9216)   softmaxed P (A-frags for PV)
//   rm/rl/ra f32 [64]  @103424  (768)
// Total 104192 B -> 2 CTAs/SM.
// Epilogue reuses smem from 0 as f32 [64][264] staging.
// ---------------------------------------------------------------------------
#define SM_Q 0
#define QS_STR 264
#define SM_K 33792
#define KS_STR 72
#define SM_V 43008
#define VS_STR 264
#define SM_S 76800
#define SS_STR 68
#define SM_P 94208
#define PS_STR 72
#define SM_R 103424
#define SM_BYTES 104192
#define VF_STR 264

__global__ __launch_bounds__(256, 2) void flash_kernel(
    const float* __restrict__ RES,
    const float* __restrict__ gamma, const float* __restrict__ beta,
    float* __restrict__ OUT)
{
    extern __shared__ char smem[];
    const uint32_t sb = smem_u32(smem);

    __nv_bfloat16* Qs = (__nv_bfloat16*)(smem + SM_Q);
    __nv_bfloat16* Ks = (__nv_bfloat16*)(smem + SM_K);
    __nv_bfloat16* Vs = (__nv_bfloat16*)(smem + SM_V);
    float*         Ss = (float*)(smem + SM_S);
    __nv_bfloat16* Ps = (__nv_bfloat16*)(smem + SM_P);
    float*         rm = (float*)(smem + SM_R);
    float*         rl = rm + 64;
    float*         ra = rl + 64;

    const int tid  = threadIdx.x;
    const int warp = tid >> 5;
    const int lane = tid & 31;
    const int ly   = lane >> 2;
    const int lx   = lane & 3;

    const int q0   = blockIdx.x << 6;
    const int base = blockIdx.y * SEQ * EDIM;
    const __nv_bfloat16* Qb = g_Q + base;
    const __nv_bfloat16* Kb = g_K + base;
    const __nv_bfloat16* Vb = g_V + base;

    // Phase-A warp tile: rows r0a..+15, keys n0a..+31
    const int r0a = (warp & 3) << 4;
    const int n0a = (warp >> 2) << 5;
    // Phase-C warp tile: rows r0c..+15, dims d0c..+127
    const int r0c = (warp & 3) << 4;
    const int d0c = (warp >> 2) << 7;

    // ---- Load Q tile [64 x 256] bf16, uint4 copies ----
    #pragma unroll
    for (int i = 0; i < 8; i++) {
        int idx = tid + i*256;
        int row = idx >> 5;
        int c8  = (idx & 31) << 3;
        uint4 q = *(const uint4*)(Qb + (q0 + row)*EDIM + c8);
        *(uint4*)(Qs + row*QS_STR + c8) = q;
    }
    if (tid < 64) { rm[tid] = -1e30f; rl[tid] = 0.0f; }

    float acc[16][4];
    #pragma unroll
    for (int nb = 0; nb < 16; nb++)
        #pragma unroll
        for (int r = 0; r < 4; r++) acc[nb][r] = 0.0f;

    // precomputed ldmatrix lane addresses (byte offsets within smem)
    // A-frags (Qs / Ps): row = base + (lane&15), col-halfs = kb16 + (lane>>4)*8
    const int a_row = lane & 15;
    const int a_k8  = (lane >> 4) << 3;
    // B-frags non-trans (Ks): n = nbase + ((lane>>4)<<3) + (lane&7), k = ((lane>>3)&1)*8
    const int b_n  = ((lane >> 4) << 3) + (lane & 7);
    const int b_k8 = ((lane >> 3) & 1) << 3;
    // B-frags trans (Vs): key = ((lane>>3)&1)*8 + (lane&7), dim += ((lane>>4)<<3)
    const int v_key = (((lane >> 3) & 1) << 3) + (lane & 7);
    const int v_d8  = (lane >> 4) << 3;

    for (int kt = 0; kt < 64; kt++) {
        const int key0 = kt << 6;

        // ================= Phase A: S = Q . K^T (bf16 mma) =================
        float sC[4][4];
        #pragma unroll
        for (int nb = 0; nb < 4; nb++)
            #pragma unroll
            for (int r = 0; r < 4; r++) sC[nb][r] = 0.0f;

        for (int kc = 0; kc < 4; kc++) {
            __syncthreads();   // prior readers of Ks/Vs done
            // K chunk: Ks[key][k] = K[key0+key][kc*64+k], k in [0,64)
            #pragma unroll
            for (int i = 0; i < 2; i++) {
                int idx = tid + i*256;
                int key = idx >> 3;
                int c8  = (idx & 7) << 3;
                uint4 kv = *(const uint4*)(Kb + (key0 + key)*EDIM + (kc<<6) + c8);
                *(uint4*)(Ks + key*KS_STR + c8) = kv;
            }
            // V quarter: rows 16*kc..+15, all 256 dims (row-major copy)
            #pragma unroll
            for (int i = 0; i < 2; i++) {
                int idx  = tid + i*256;
                int vrow = (kc << 4) + (idx >> 5);
                int c8   = (idx & 31) << 3;
                uint4 vv = *(const uint4*)(Vb + (key0 + vrow)*EDIM + c8);
                *(uint4*)(Vs + vrow*VS_STR + c8) = vv;
            }
            __syncthreads();

            #pragma unroll
            for (int kb = 0; kb < 4; kb++) {
                uint32_t a0, a1, a2, a3;
                uint32_t aaddr = sb + SM_Q
                    + ((r0a + a_row)*QS_STR + (kc<<6) + (kb<<4) + a_k8) * 2;
                ldsm_x4(a0, a1, a2, a3, aaddr);
                #pragma unroll
                for (int h = 0; h < 2; h++) {
                    uint32_t b0, b1, b2, b3;
                    uint32_t baddr = sb + SM_K
                        + ((n0a + (h<<4) + b_n)*KS_STR + (kb<<4) + b_k8) * 2;
                    ldsm_x4(b0, b1, b2, b3, baddr);
                    mma_bf16(sC[2*h    ], a0, a1, a2, a3, b0, b1);
                    mma_bf16(sC[2*h + 1], a0, a1, a2, a3, b2, b3);
                }
            }
        }

        // store scaled scores to Ss (scale = 1/sqrt(4096) = 1/64)
        {
            const float scale = 0.015625f;
            #pragma unroll
            for (int nb = 0; nb < 4; nb++) {
                const int col = n0a + (nb << 3) + (lx << 1);
                *(float2*)(Ss + (r0a + ly    )*SS_STR + col) =
                    make_float2(sC[nb][0]*scale, sC[nb][1]*scale);
                *(float2*)(Ss + (r0a + ly + 8)*SS_STR + col) =
                    make_float2(sC[nb][2]*scale, sC[nb][3]*scale);
            }
        }
        __syncthreads();

        // ============ Phase B: online softmax (4 threads/row), P -> bf16 =====
        {
            const int row = tid >> 2;
            const int qq  = tid & 3;
            float* srow = Ss + row*SS_STR + (qq << 4);
            float4 v0 = *(float4*)(srow + 0);
            float4 v1 = *(float4*)(srow + 4);
            float4 v2 = *(float4*)(srow + 8);
            float4 v3 = *(float4*)(srow + 12);
            float mo = rm[row];
            float mx = fmaxf(fmaxf(fmaxf(v0.x, v0.y), fmaxf(v0.z, v0.w)),
                             fmaxf(fmaxf(v1.x, v1.y), fmaxf(v1.z, v1.w)));
            mx = fmaxf(mx, fmaxf(fmaxf(fmaxf(v2.x, v2.y), fmaxf(v2.z, v2.w)),
                                 fmaxf(fmaxf(v3.x, v3.y), fmaxf(v3.z, v3.w))));
            mx = fmaxf(mx, __shfl_xor_sync(0xffffffffu, mx, 1));
            mx = fmaxf(mx, __shfl_xor_sync(0xffffffffu, mx, 2));
            mx = fmaxf(mx, mo);
            v0.x = __expf(v0.x - mx); v0.y = __expf(v0.y - mx);
            v0.z = __expf(v0.z - mx); v0.w = __expf(v0.w - mx);
            v1.x = __expf(v1.x - mx); v1.y = __expf(v1.y - mx);
            v1.z = __expf(v1.z - mx); v1.w = __expf(v1.w - mx);
            v2.x = __expf(v2.x - mx); v2.y = __expf(v2.y - mx);
            v2.z = __expf(v2.z - mx); v2.w = __expf(v2.w - mx);
            v3.x = __expf(v3.x - mx); v3.y = __expf(v3.y - mx);
            v3.z = __expf(v3.z - mx); v3.w = __expf(v3.w - mx);
            float s = v0.x+v0.y+v0.z+v0.w + v1.x+v1.y+v1.z+v1.w
                    + v2.x+v2.y+v2.z+v2.w + v3.x+v3.y+v3.z+v3.w;
            s += __shfl_xor_sync(0xffffffffu, s, 1);
            s += __shfl_xor_sync(0xffffffffu, s, 2);
            // write P as bf16 into Ps
            __nv_bfloat162 p0 = __floats2bfloat162_rn(v0.x, v0.y);
            __nv_bfloat162 p1 = __floats2bfloat162_rn(v0.z, v0.w);
            __nv_bfloat162 p2 = __floats2bfloat162_rn(v1.x, v1.y);
            __nv_bfloat162 p3 = __floats2bfloat162_rn(v1.z, v1.w);
            __nv_bfloat162 p4 = __floats2bfloat162_rn(v2.x, v2.y);
            __nv_bfloat162 p5 = __floats2bfloat162_rn(v2.z, v2.w);
            __nv_bfloat162 p6 = __floats2bfloat162_rn(v3.x, v3.y);
            __nv_bfloat162 p7 = __floats2bfloat162_rn(v3.z, v3.w);
            uint4 w0, w1;
            w0.x = *(uint32_t*)&p0; w0.y = *(uint32_t*)&p1;
            w0.z = *(uint32_t*)&p2; w0.w = *(uint32_t*)&p3;
            w1.x = *(uint32_t*)&p4; w1.y = *(uint32_t*)&p5;
            w1.z = *(uint32_t*)&p6; w1.w = *(uint32_t*)&p7;
            *(uint4*)(Ps + row*PS_STR + (qq << 4))     = w0;
            *(uint4*)(Ps + row*PS_STR + (qq << 4) + 8) = w1;
            if (qq == 0) {
                float alpha = __expf(mo - mx);
                rm[row] = mx;
                rl[row] = rl[row]*alpha + s;
                ra[row] = alpha;
            }
        }
        __syncthreads();

        // ================= Phase C: O += P . V (bf16 mma) ===================
        {
            float al0 = ra[r0c + ly];
            float al1 = ra[r0c + ly + 8];
            #pragma unroll
            for (int nb = 0; nb < 16; nb++) {
                acc[nb][0] *= al0; acc[nb][1] *= al0;
                acc[nb][2] *= al1; acc[nb][3] *= al1;
            }
        }
        #pragma unroll
        for (int kb = 0; kb < 4; kb++) {
            uint32_t a0, a1, a2, a3;
            uint32_t aaddr = sb + SM_P
                + ((r0c + a_row)*PS_STR + (kb<<4) + a_k8) * 2;
            ldsm_x4(a0, a1, a2, a3, aaddr);
            #pragma unroll
            for (int bp = 0; bp < 8; bp++) {
                uint32_t b0, b1, b2, b3;
                uint32_t baddr = sb + SM_V
                    + (((kb<<4) + v_key)*VS_STR + d0c + (bp<<4) + v_d8) * 2;
                ldsm_x4t(b0, b1, b2, b3, baddr);
                mma_bf16(acc[2*bp    ], a0, a1, a2, a3, b0, b1);
                mma_bf16(acc[2*bp + 1], a0, a1, a2, a3, b2, b3);
            }
        }
    }
    __syncthreads();

    // ---- Epilogue: scatter h = acc/rl into f32 staging, residual + LayerNorm ----
    float* Vf = (float*)smem;   // [64][VF_STR] f32, reuses Qs/Ks/Vs space
    {
        float il0 = 1.0f / rl[r0c + ly];
        float il1 = 1.0f / rl[r0c + ly + 8];
        #pragma unroll
        for (int nb = 0; nb < 16; nb++) {
            const int n = d0c + (nb << 3) + (lx << 1);
            *(float2*)(Vf + (r0c + ly    )*VF_STR + n) =
                make_float2(acc[nb][0]*il0, acc[nb][1]*il0);
            *(float2*)(Vf + (r0c + ly + 8)*VF_STR + n) =
                make_float2(acc[nb][2]*il1, acc[nb][3]*il1);
        }
    }
    __syncthreads();

    #pragma unroll
    for (int rr = 0; rr < 8; rr++) {
        const int row = (warp << 3) + rr;
        const int d   = lane << 3;
        float4 h0 = *(float4*)(Vf + row*VF_STR + d);
        float4 h1 = *(float4*)(Vf + row*VF_STR + d + 4);
        const float* resrow = RES + base + (q0 + row)*EDIM + d;
        float4 x0 = *(const float4*)(resrow);
        float4 x1 = *(const float4*)(resrow + 4);
        h0.x += x0.x; h0.y += x0.y; h0.z += x0.z; h0.w += x0.w;
        h1.x += x1.x; h1.y += x1.y; h1.z += x1.z; h1.w += x1.w;
        float s1 = h0.x+h0.y+h0.z+h0.w + h1.x+h1.y+h1.z+h1.w;
        float s2 = h0.x*h0.x + h0.y*h0.y + h0.z*h0.z + h0.w*h0.w
                 + h1.x*h1.x + h1.y*h1.y + h1.z*h1.z + h1.w*h1.w;
        #pragma unroll
        for (int off = 16; off >= 1; off >>= 1) {
            s1 += __shfl_xor_sync(0xffffffffu, s1, off);
            s2 += __shfl_xor_sync(0xffffffffu, s2, off);
        }
        const float mu  = s1 * (1.0f/256.0f);
        const float var = s2 * (1.0f/256.0f) - mu*mu;
        const float rs  = rsqrtf(var + 1e-5f);
        float4 g0 = *(const float4*)(gamma + d);
        float4 g1 = *(const float4*)(gamma + d + 4);
        float4 b0 = *(const float4*)(beta + d);
        float4 b1 = *(const float4*)(beta + d + 4);
        float4 o0, o1;
        o0.x = (h0.x-mu)*rs*g0.x + b0.x;  o0.y = (h0.y-mu)*rs*g0.y + b0.y;
        o0.z = (h0.z-mu)*rs*g0.z + b0.z;  o0.w = (h0.w-mu)*rs*g0.w + b0.w;
        o1.x = (h1.x-mu)*rs*g1.x + b1.x;  o1.y = (h1.y-mu)*rs*g1.y + b1.y;
        o1.z = (h1.z-mu)*rs*g1.z + b1.z;  o1.w = (h1.w-mu)*rs*g1.w + b1.w;
        float* orow = OUT + base + (q0 + row)*EDIM + d;
        *(float4*)(orow)     = o0;
        *(float4*)(orow + 4) = o1;
    }
}

// ---------------------------------------------------------------------------
extern "C" void kernel_launch(void* const* d_in, const int* in_sizes, int n_in,
                              void* d_out, int out_size) {
    const float* x     = (const float*)d_in[0];
    const float* Wq1   = (const float*)d_in[1];
    const float* bq1   = (const float*)d_in[2];
    const float* Wk1   = (const float*)d_in[3];
    const float* bk1   = (const float*)d_in[4];
    const float* Wv1   = (const float*)d_in[5];
    const float* bv1   = (const float*)d_in[6];
    const float* Wq2   = (const float*)d_in[7];
    const float* bq2   = (const float*)d_in[8];
    const float* Wk2   = (const float*)d_in[9];
    const float* bk2   = (const float*)d_in[10];
    const float* Wv2   = (const float*)d_in[11];
    const float* bv2   = (const float*)d_in[12];
    const float* g1    = (const float*)d_in[13];
    const float* beta1 = (const float*)d_in[14];
    const float* g2    = (const float*)d_in[15];
    const float* beta2 = (const float*)d_in[16];
    float* out = (float*)d_out;

    float* O = nullptr;
    cudaGetSymbolAddress((void**)&O, g_O);

    cudaFuncSetAttribute(flash_kernel, cudaFuncAttributeMaxDynamicSharedMemorySize, SM_BYTES);

    dim3 pg(NTOK/64, 12), pb(256);
    dim3 fg(SEQ/64, BATCH), fb(256);

    // Layer 1
    proj_kernel<<<pg, pb>>>(x, Wq1, bq1, Wk1, bk1, Wv1, bv1);
    flash_kernel<<<fg, fb, SM_BYTES>>>(x, g1, beta1, O);
    // Layer 2
    proj_kernel<<<pg, pb>>>(O, Wq2, bq2, Wk2, bk2, Wv2, bv2);
    flash_kernel<<<fg, fb, SM_BYTES>>>(O, g2, beta2, out);
}

// round 9
// speedup vs baseline: 2.2601x; 1.0030x over previous
#include <cuda_runtime.h>
#include <cuda_bf16.h>
#include <cstdint>

#define BATCH 4
#define SEQ   4096
#define EDIM  256
#define NTOK  (BATCH*SEQ)

// Scratch (device globals: no allocation allowed in kernel_launch)
__device__ __nv_bfloat16 g_Q[NTOK*EDIM];
__device__ __nv_bfloat16 g_K[NTOK*EDIM];
__device__ __nv_bfloat16 g_V[NTOK*EDIM];
__device__ float         g_O[NTOK*EDIM];

// ---------------------------------------------------------------------------
// mma / ldmatrix helpers (bf16 m16n8k16, fp32 accum)
// ---------------------------------------------------------------------------
__device__ __forceinline__ uint32_t smem_u32(const void* p) {
    uint32_t a;
    asm("{ .reg .u64 t; cvta.to.shared.u64 t, %1; cvt.u32.u64 %0, t; }" : "=r"(a) : "l"(p));
    return a;
}

__device__ __forceinline__ void mma_bf16(float* c,
                                         uint32_t a0, uint32_t a1, uint32_t a2, uint32_t a3,
                                         uint32_t b0, uint32_t b1) {
    asm volatile(
        "mma.sync.aligned.m16n8k16.row.col.f32.bf16.bf16.f32 "
        "{%0,%1,%2,%3}, {%4,%5,%6,%7}, {%8,%9}, {%0,%1,%2,%3};"
        : "+f"(c[0]), "+f"(c[1]), "+f"(c[2]), "+f"(c[3])
        : "r"(a0), "r"(a1), "r"(a2), "r"(a3), "r"(b0), "r"(b1));
}

__device__ __forceinline__ void ldsm_x4(uint32_t& r0, uint32_t& r1, uint32_t& r2, uint32_t& r3,
                                        uint32_t addr) {
    asm volatile("ldmatrix.sync.aligned.m8n8.x4.shared.b16 {%0,%1,%2,%3}, [%4];"
                 : "=r"(r0), "=r"(r1), "=r"(r2), "=r"(r3) : "r"(addr));
}

__device__ __forceinline__ void ldsm_x4t(uint32_t& r0, uint32_t& r1, uint32_t& r2, uint32_t& r3,
                                         uint32_t addr) {
    asm volatile("ldmatrix.sync.aligned.m8n8.x4.trans.shared.b16 {%0,%1,%2,%3}, [%4];"
                 : "=r"(r0), "=r"(r1), "=r"(r2), "=r"(r3) : "r"(addr));
}

// ---------------------------------------------------------------------------
// Fused QKV projection (FFMA) — now emits bf16 outputs.
// Y[m,n] = bf16( sum_k X[m,k]*W[n,k] + b[n] )
// ---------------------------------------------------------------------------
__global__ __launch_bounds__(256) void proj_kernel(
    const float* __restrict__ X,
    const float* __restrict__ Wq, const float* __restrict__ bq,
    const float* __restrict__ Wk, const float* __restrict__ bk,
    const float* __restrict__ Wv, const float* __restrict__ bv)
{
    __shared__ __align__(16) float Xt[32*68];
    __shared__ __align__(16) float Wt[32*68];

    const int mt    = blockIdx.x;
    const int nt    = blockIdx.y;
    const int which = nt >> 2;
    const int n0    = (nt & 3) << 6;
    const int m0    = mt << 6;

    const float* W    = (which == 0) ? Wq : (which == 1) ? Wk : Wv;
    const float* bias = (which == 0) ? bq : (which == 1) ? bk : bv;
    __nv_bfloat16* Y  = (which == 0) ? g_Q : (which == 1) ? g_K : g_V;

    const int tid = threadIdx.x;
    const int tx  = tid & 15;
    const int ty  = tid >> 4;

    float acc[4][4] = {};

    for (int kk = 0; kk < EDIM; kk += 32) {
        __syncthreads();
        #pragma unroll
        for (int e = 0; e < 8; e++) {
            int idx = tid + e*256;
            int m = idx >> 5;
            int k = idx & 31;
            Xt[k*68 + m] = X[(m0+m)*EDIM + kk + k];
            Wt[k*68 + m] = W[(n0+m)*EDIM + kk + k];
        }
        __syncthreads();
        #pragma unroll 8
        for (int k = 0; k < 32; k++) {
            float4 a4 = *(const float4*)(Xt + k*68 + 4*ty);
            float4 b4 = *(const float4*)(Wt + k*68 + 4*tx);
            float a[4] = {a4.x, a4.y, a4.z, a4.w};
            float b[4] = {b4.x, b4.y, b4.z, b4.w};
            #pragma unroll
            for (int i = 0; i < 4; i++)
                #pragma unroll
                for (int j = 0; j < 4; j++)
                    acc[i][j] = fmaf(a[i], b[j], acc[i][j]);
        }
    }

    float4 bv4 = *(const float4*)(bias + n0 + 4*tx);
    #pragma unroll
    for (int i = 0; i < 4; i++) {
        __nv_bfloat162 p0 = __floats2bfloat162_rn(acc[i][0] + bv4.x, acc[i][1] + bv4.y);
        __nv_bfloat162 p1 = __floats2bfloat162_rn(acc[i][2] + bv4.z, acc[i][3] + bv4.w);
        uint2 pk;
        pk.x = *(uint32_t*)&p0;
        pk.y = *(uint32_t*)&p1;
        *(uint2*)(Y + (m0 + 4*ty + i)*EDIM + n0 + 4*tx) = pk;
    }
}

// ---------------------------------------------------------------------------
// bf16 mma.sync flash attention + fused residual/LayerNorm.
// CTA: 64 queries, 8 warps (256 threads), key tiles of 64, K chunked by 64.
//
// Smem (dynamic, bytes):
//   Qs bf16 [64][264]  @0       (33792)  A-frags, stride 264h = 132w == 4 mod 32
//   Ks bf16 [64][72]   @33792   (9216)   B-frags (K chunk, k-major rows)
//   Vs bf16 [64][264]  @43008   (33792)  B-frags via ldmatrix.trans (row-major)
//   Ss f32  [64][68]   @76800   (17408)  raw scores
//   Ps bf16 [64][72]   @94208   (9216)   softmaxed P (A-frags for PV)
//   rm/rl/ra f32 [64]  @103424  (768)
// Total 104192 B -> 2 CTAs/SM.
// Epilogue reuses smem from 0 as f32 [64][264] staging.
// ---------------------------------------------------------------------------
#define SM_Q 0
#define QS_STR 264
#define SM_K 33792
#define KS_STR 72
#define SM_V 43008
#define VS_STR 264
#define SM_S 76800
#define SS_STR 68
#define SM_P 94208
#define PS_STR 72
#define SM_R 103424
#define SM_BYTES 104192
#define VF_STR 264

__global__ __launch_bounds__(256, 2) void flash_kernel(
    const float* __restrict__ RES,
    const float* __restrict__ gamma, const float* __restrict__ beta,
    float* __restrict__ OUT)
{
    extern __shared__ char smem[];
    const uint32_t sb = smem_u32(smem);

    __nv_bfloat16* Qs = (__nv_bfloat16*)(smem + SM_Q);
    __nv_bfloat16* Ks = (__nv_bfloat16*)(smem + SM_K);
    __nv_bfloat16* Vs = (__nv_bfloat16*)(smem + SM_V);
    float*         Ss = (float*)(smem + SM_S);
    __nv_bfloat16* Ps = (__nv_bfloat16*)(smem + SM_P);
    float*         rm = (float*)(smem + SM_R);
    float*         rl = rm + 64;
    float*         ra = rl + 64;

    const int tid  = threadIdx.x;
    const int warp = tid >> 5;
    const int lane = tid & 31;
    const int ly   = lane >> 2;
    const int lx   = lane & 3;

    const int q0   = blockIdx.x << 6;
    const int base = blockIdx.y * SEQ * EDIM;
    const __nv_bfloat16* Qb = g_Q + base;
    const __nv_bfloat16* Kb = g_K + base;
    const __nv_bfloat16* Vb = g_V + base;

    // Phase-A warp tile: rows r0a..+15, keys n0a..+31
    const int r0a = (warp & 3) << 4;
    const int n0a = (warp >> 2) << 5;
    // Phase-C warp tile: rows r0c..+15, dims d0c..+127
    const int r0c = (warp & 3) << 4;
    const int d0c = (warp >> 2) << 7;

    // ---- Load Q tile [64 x 256] bf16, uint4 copies ----
    #pragma unroll
    for (int i = 0; i < 8; i++) {
        int idx = tid + i*256;
        int row = idx >> 5;
        int c8  = (idx & 31) << 3;
        uint4 q = *(const uint4*)(Qb + (q0 + row)*EDIM + c8);
        *(uint4*)(Qs + row*QS_STR + c8) = q;
    }
    if (tid < 64) { rm[tid] = -1e30f; rl[tid] = 0.0f; }

    float acc[16][4];
    #pragma unroll
    for (int nb = 0; nb < 16; nb++)
        #pragma unroll
        for (int r = 0; r < 4; r++) acc[nb][r] = 0.0f;

    // precomputed ldmatrix lane addresses (byte offsets within smem)
    // A-frags (Qs / Ps): row = base + (lane&15), col-halfs = kb16 + (lane>>4)*8
    const int a_row = lane & 15;
    const int a_k8  = (lane >> 4) << 3;
    // B-frags non-trans (Ks): n = nbase + ((lane>>4)<<3) + (lane&7), k = ((lane>>3)&1)*8
    const int b_n  = ((lane >> 4) << 3) + (lane & 7);
    const int b_k8 = ((lane >> 3) & 1) << 3;
    // B-frags trans (Vs): key = ((lane>>3)&1)*8 + (lane&7), dim += ((lane>>4)<<3)
    const int v_key = (((lane >> 3) & 1) << 3) + (lane & 7);
    const int v_d8  = (lane >> 4) << 3;

    for (int kt = 0; kt < 64; kt++) {
        const int key0 = kt << 6;

        // ================= Phase A: S = Q . K^T (bf16 mma) =================
        float sC[4][4];
        #pragma unroll
        for (int nb = 0; nb < 4; nb++)
            #pragma unroll
            for (int r = 0; r < 4; r++) sC[nb][r] = 0.0f;

        for (int kc = 0; kc < 4; kc++) {
            __syncthreads();   // prior readers of Ks/Vs done
            // K chunk: Ks[key][k] = K[key0+key][kc*64+k], k in [0,64)
            #pragma unroll
            for (int i = 0; i < 2; i++) {
                int idx = tid + i*256;
                int key = idx >> 3;
                int c8  = (idx & 7) << 3;
                uint4 kv = *(const uint4*)(Kb + (key0 + key)*EDIM + (kc<<6) + c8);
                *(uint4*)(Ks + key*KS_STR + c8) = kv;
            }
            // V quarter: rows 16*kc..+15, all 256 dims (row-major copy)
            #pragma unroll
            for (int i = 0; i < 2; i++) {
                int idx  = tid + i*256;
                int vrow = (kc << 4) + (idx >> 5);
                int c8   = (idx & 31) << 3;
                uint4 vv = *(const uint4*)(Vb + (key0 + vrow)*EDIM + c8);
                *(uint4*)(Vs + vrow*VS_STR + c8) = vv;
            }
            __syncthreads();

            #pragma unroll
            for (int kb = 0; kb < 4; kb++) {
                uint32_t a0, a1, a2, a3;
                uint32_t aaddr = sb + SM_Q
                    + ((r0a + a_row)*QS_STR + (kc<<6) + (kb<<4) + a_k8) * 2;
                ldsm_x4(a0, a1, a2, a3, aaddr);
                #pragma unroll
                for (int h = 0; h < 2; h++) {
                    uint32_t b0, b1, b2, b3;
                    uint32_t baddr = sb + SM_K
                        + ((n0a + (h<<4) + b_n)*KS_STR + (kb<<4) + b_k8) * 2;
                    ldsm_x4(b0, b1, b2, b3, baddr);
                    mma_bf16(sC[2*h    ], a0, a1, a2, a3, b0, b1);
                    mma_bf16(sC[2*h + 1], a0, a1, a2, a3, b2, b3);
                }
            }
        }

        // store scaled scores to Ss (scale = 1/sqrt(4096) = 1/64)
        {
            const float scale = 0.015625f;
            #pragma unroll
            for (int nb = 0; nb < 4; nb++) {
                const int col = n0a + (nb << 3) + (lx << 1);
                *(float2*)(Ss + (r0a + ly    )*SS_STR + col) =
                    make_float2(sC[nb][0]*scale, sC[nb][1]*scale);
                *(float2*)(Ss + (r0a + ly + 8)*SS_STR + col) =
                    make_float2(sC[nb][2]*scale, sC[nb][3]*scale);
            }
        }
        __syncthreads();

        // ============ Phase B: online softmax (4 threads/row), P -> bf16 =====
        {
            const int row = tid >> 2;
            const int qq  = tid & 3;
            float* srow = Ss + row*SS_STR + (qq << 4);
            float4 v0 = *(float4*)(srow + 0);
            float4 v1 = *(float4*)(srow + 4);
            float4 v2 = *(float4*)(srow + 8);
            float4 v3 = *(float4*)(srow + 12);
            float mo = rm[row];
            float mx = fmaxf(fmaxf(fmaxf(v0.x, v0.y), fmaxf(v0.z, v0.w)),
                             fmaxf(fmaxf(v1.x, v1.y), fmaxf(v1.z, v1.w)));
            mx = fmaxf(mx, fmaxf(fmaxf(fmaxf(v2.x, v2.y), fmaxf(v2.z, v2.w)),
                                 fmaxf(fmaxf(v3.x, v3.y), fmaxf(v3.z, v3.w))));
            mx = fmaxf(mx, __shfl_xor_sync(0xffffffffu, mx, 1));
            mx = fmaxf(mx, __shfl_xor_sync(0xffffffffu, mx, 2));
            mx = fmaxf(mx, mo);
            v0.x = __expf(v0.x - mx); v0.y = __expf(v0.y - mx);
            v0.z = __expf(v0.z - mx); v0.w = __expf(v0.w - mx);
            v1.x = __expf(v1.x - mx); v1.y = __expf(v1.y - mx);
            v1.z = __expf(v1.z - mx); v1.w = __expf(v1.w - mx);
            v2.x = __expf(v2.x - mx); v2.y = __expf(v2.y - mx);
            v2.z = __expf(v2.z - mx); v2.w = __expf(v2.w - mx);
            v3.x = __expf(v3.x - mx); v3.y = __expf(v3.y - mx);
            v3.z = __expf(v3.z - mx); v3.w = __expf(v3.w - mx);
            float s = v0.x+v0.y+v0.z+v0.w + v1.x+v1.y+v1.z+v1.w
                    + v2.x+v2.y+v2.z+v2.w + v3.x+v3.y+v3.z+v3.w;
            s += __shfl_xor_sync(0xffffffffu, s, 1);
            s += __shfl_xor_sync(0xffffffffu, s, 2);
            // write P as bf16 into Ps
            __nv_bfloat162 p0 = __floats2bfloat162_rn(v0.x, v0.y);
            __nv_bfloat162 p1 = __floats2bfloat162_rn(v0.z, v0.w);
            __nv_bfloat162 p2 = __floats2bfloat162_rn(v1.x, v1.y);
            __nv_bfloat162 p3 = __floats2bfloat162_rn(v1.z, v1.w);
            __nv_bfloat162 p4 = __floats2bfloat162_rn(v2.x, v2.y);
            __nv_bfloat162 p5 = __floats2bfloat162_rn(v2.z, v2.w);
            __nv_bfloat162 p6 = __floats2bfloat162_rn(v3.x, v3.y);
            __nv_bfloat162 p7 = __floats2bfloat162_rn(v3.z, v3.w);
            uint4 w0, w1;
            w0.x = *(uint32_t*)&p0; w0.y = *(uint32_t*)&p1;
            w0.z = *(uint32_t*)&p2; w0.w = *(uint32_t*)&p3;
            w1.x = *(uint32_t*)&p4; w1.y = *(uint32_t*)&p5;
            w1.z = *(uint32_t*)&p6; w1.w = *(uint32_t*)&p7;
            *(uint4*)(Ps + row*PS_STR + (qq << 4))     = w0;
            *(uint4*)(Ps + row*PS_STR + (qq << 4) + 8) = w1;
            if (qq == 0) {
                float alpha = __expf(mo - mx);
                rm[row] = mx;
                rl[row] = rl[row]*alpha + s;
                ra[row] = alpha;
            }
        }
        __syncthreads();

        // ================= Phase C: O += P . V (bf16 mma) ===================
        {
            float al0 = ra[r0c + ly];
            float al1 = ra[r0c + ly + 8];
            #pragma unroll
            for (int nb = 0; nb < 16; nb++) {
                acc[nb][0] *= al0; acc[nb][1] *= al0;
                acc[nb][2] *= al1; acc[nb][3] *= al1;
            }
        }
        #pragma unroll
        for (int kb = 0; kb < 4; kb++) {
            uint32_t a0, a1, a2, a3;
            uint32_t aaddr = sb + SM_P
                + ((r0c + a_row)*PS_STR + (kb<<4) + a_k8) * 2;
            ldsm_x4(a0, a1, a2, a3, aaddr);
            #pragma unroll
            for (int bp = 0; bp < 8; bp++) {
                uint32_t b0, b1, b2, b3;
                uint32_t baddr = sb + SM_V
                    + (((kb<<4) + v_key)*VS_STR + d0c + (bp<<4) + v_d8) * 2;
                ldsm_x4t(b0, b1, b2, b3, baddr);
                mma_bf16(acc[2*bp    ], a0, a1, a2, a3, b0, b1);
                mma_bf16(acc[2*bp + 1], a0, a1, a2, a3, b2, b3);
            }
        }
    }
    __syncthreads();

    // ---- Epilogue: scatter h = acc/rl into f32 staging, residual + LayerNorm ----
    float* Vf = (float*)smem;   // [64][VF_STR] f32, reuses Qs/Ks/Vs space
    {
        float il0 = 1.0f / rl[r0c + ly];
        float il1 = 1.0f / rl[r0c + ly + 8];
        #pragma unroll
        for (int nb = 0; nb < 16; nb++) {
            const int n = d0c + (nb << 3) + (lx << 1);
            *(float2*)(Vf + (r0c + ly    )*VF_STR + n) =
                make_float2(acc[nb][0]*il0, acc[nb][1]*il0);
            *(float2*)(Vf + (r0c + ly + 8)*VF_STR + n) =
                make_float2(acc[nb][2]*il1, acc[nb][3]*il1);
        }
    }
    __syncthreads();

    #pragma unroll
    for (int rr = 0; rr < 8; rr++) {
        const int row = (warp << 3) + rr;
        const int d   = lane << 3;
        float4 h0 = *(float4*)(Vf + row*VF_STR + d);
        float4 h1 = *(float4*)(Vf + row*VF_STR + d + 4);
        const float* resrow = RES + base + (q0 + row)*EDIM + d;
        float4 x0 = *(const float4*)(resrow);
        float4 x1 = *(const float4*)(resrow + 4);
        h0.x += x0.x; h0.y += x0.y; h0.z += x0.z; h0.w += x0.w;
        h1.x += x1.x; h1.y += x1.y; h1.z += x1.z; h1.w += x1.w;
        float s1 = h0.x+h0.y+h0.z+h0.w + h1.x+h1.y+h1.z+h1.w;
        float s2 = h0.x*h0.x + h0.y*h0.y + h0.z*h0.z + h0.w*h0.w
                 + h1.x*h1.x + h1.y*h1.y + h1.z*h1.z + h1.w*h1.w;
        #pragma unroll
        for (int off = 16; off >= 1; off >>= 1) {
            s1 += __shfl_xor_sync(0xffffffffu, s1, off);
            s2 += __shfl_xor_sync(0xffffffffu, s2, off);
        }
        const float mu  = s1 * (1.0f/256.0f);
        const float var = s2 * (1.0f/256.0f) - mu*mu;
        const float rs  = rsqrtf(var + 1e-5f);
        float4 g0 = *(const float4*)(gamma + d);
        float4 g1 = *(const float4*)(gamma + d + 4);
        float4 b0 = *(const float4*)(beta + d);
        float4 b1 = *(const float4*)(beta + d + 4);
        float4 o0, o1;
        o0.x = (h0.x-mu)*rs*g0.x + b0.x;  o0.y = (h0.y-mu)*rs*g0.y + b0.y;
        o0.z = (h0.z-mu)*rs*g0.z + b0.z;  o0.w = (h0.w-mu)*rs*g0.w + b0.w;
        o1.x = (h1.x-mu)*rs*g1.x + b1.x;  o1.y = (h1.y-mu)*rs*g1.y + b1.y;
        o1.z = (h1.z-mu)*rs*g1.z + b1.z;  o1.w = (h1.w-mu)*rs*g1.w + b1.w;
        float* orow = OUT + base + (q0 + row)*EDIM + d;
        *(float4*)(orow)     = o0;
        *(float4*)(orow + 4) = o1;
    }
}

// ---------------------------------------------------------------------------
extern "C" void kernel_launch(void* const* d_in, const int* in_sizes, int n_in,
                              void* d_out, int out_size) {
    const float* x     = (const float*)d_in[0];
    const float* Wq1   = (const float*)d_in[1];
    const float* bq1   = (const float*)d_in[2];
    const float* Wk1   = (const float*)d_in[3];
    const float* bk1   = (const float*)d_in[4];
    const float* Wv1   = (const float*)d_in[5];
    const float* bv1   = (const float*)d_in[6];
    const float* Wq2   = (const float*)d_in[7];
    const float* bq2   = (const float*)d_in[8];
    const float* Wk2   = (const float*)d_in[9];
    const float* bk2   = (const float*)d_in[10];
    const float* Wv2   = (const float*)d_in[11];
    const float* bv2   = (const float*)d_in[12];
    const float* g1    = (const float*)d_in[13];
    const float* beta1 = (const float*)d_in[14];
    const float* g2    = (const float*)d_in[15];
    const float* beta2 = (const float*)d_in[16];
    float* out = (float*)d_out;

    float* O = nullptr;
    cudaGetSymbolAddress((void**)&O, g_O);

    cudaFuncSetAttribute(flash_kernel, cudaFuncAttributeMaxDynamicSharedMemorySize, SM_BYTES);

    dim3 pg(NTOK/64, 12), pb(256);
    dim3 fg(SEQ/64, BATCH), fb(256);

    // Layer 1
    proj_kernel<<<pg, pb>>>(x, Wq1, bq1, Wk1, bk1, Wv1, bv1);
    flash_kernel<<<fg, fb, SM_BYTES>>>(x, g1, beta1, O);
    // Layer 2
    proj_kernel<<<pg, pb>>>(O, Wq2, bq2, Wk2, bk2, Wv2, bv2);
    flash_kernel<<<fg, fb, SM_BYTES>>>(O, g2, beta2, out);
}

// round 14
// speedup vs baseline: 2.7329x; 1.2092x over previous
#include <cuda_runtime.h>
#include <cuda_bf16.h>
#include <cstdint>

#define BATCH 4
#define SEQ   4096
#define EDIM  256
#define NTOK  (BATCH*SEQ)

// Scratch (device globals: no allocation allowed in kernel_launch)
__device__ __nv_bfloat16 g_Q[NTOK*EDIM];
__device__ __nv_bfloat16 g_K[NTOK*EDIM];
__device__ __nv_bfloat16 g_V[NTOK*EDIM];
__device__ float         g_O[NTOK*EDIM];

// ---------------------------------------------------------------------------
// mma / ldmatrix helpers (bf16 m16n8k16, fp32 accum)
// ---------------------------------------------------------------------------
__device__ __forceinline__ uint32_t smem_u32(const void* p) {
    uint32_t a;
    asm("{ .reg .u64 t; cvta.to.shared.u64 t, %1; cvt.u32.u64 %0, t; }" : "=r"(a) : "l"(p));
    return a;
}

__device__ __forceinline__ void mma_bf16(float* c,
                                         uint32_t a0, uint32_t a1, uint32_t a2, uint32_t a3,
                                         uint32_t b0, uint32_t b1) {
    asm volatile(
        "mma.sync.aligned.m16n8k16.row.col.f32.bf16.bf16.f32 "
        "{%0,%1,%2,%3}, {%4,%5,%6,%7}, {%8,%9}, {%0,%1,%2,%3};"
        : "+f"(c[0]), "+f"(c[1]), "+f"(c[2]), "+f"(c[3])
        : "r"(a0), "r"(a1), "r"(a2), "r"(a3), "r"(b0), "r"(b1));
}

__device__ __forceinline__ void ldsm_x4(uint32_t& r0, uint32_t& r1, uint32_t& r2, uint32_t& r3,
                                        uint32_t addr) {
    asm volatile("ldmatrix.sync.aligned.m8n8.x4.shared.b16 {%0,%1,%2,%3}, [%4];"
                 : "=r"(r0), "=r"(r1), "=r"(r2), "=r"(r3) : "r"(addr));
}

__device__ __forceinline__ void ldsm_x4t(uint32_t& r0, uint32_t& r1, uint32_t& r2, uint32_t& r3,
                                         uint32_t addr) {
    asm volatile("ldmatrix.sync.aligned.m8n8.x4.trans.shared.b16 {%0,%1,%2,%3}, [%4];"
                 : "=r"(r0), "=r"(r1), "=r"(r2), "=r"(r3) : "r"(addr));
}

#define BAR1_SYNC() asm volatile("bar.sync 1, 256;" ::: "memory")

// ---------------------------------------------------------------------------
// Fused QKV projection (FFMA) — emits bf16 outputs.
// ---------------------------------------------------------------------------
__global__ __launch_bounds__(256) void proj_kernel(
    const float* __restrict__ X,
    const float* __restrict__ Wq, const float* __restrict__ bq,
    const float* __restrict__ Wk, const float* __restrict__ bk,
    const float* __restrict__ Wv, const float* __restrict__ bv)
{
    __shared__ __align__(16) float Xt[32*68];
    __shared__ __align__(16) float Wt[32*68];

    const int mt    = blockIdx.x;
    const int nt    = blockIdx.y;
    const int which = nt >> 2;
    const int n0    = (nt & 3) << 6;
    const int m0    = mt << 6;

    const float* W    = (which == 0) ? Wq : (which == 1) ? Wk : Wv;
    const float* bias = (which == 0) ? bq : (which == 1) ? bk : bv;
    __nv_bfloat16* Y  = (which == 0) ? g_Q : (which == 1) ? g_K : g_V;

    const int tid = threadIdx.x;
    const int tx  = tid & 15;
    const int ty  = tid >> 4;

    float acc[4][4] = {};

    for (int kk = 0; kk < EDIM; kk += 32) {
        __syncthreads();
        #pragma unroll
        for (int e = 0; e < 8; e++) {
            int idx = tid + e*256;
            int m = idx >> 5;
            int k = idx & 31;
            Xt[k*68 + m] = X[(m0+m)*EDIM + kk + k];
            Wt[k*68 + m] = W[(n0+m)*EDIM + kk + k];
        }
        __syncthreads();
        #pragma unroll 8
        for (int k = 0; k < 32; k++) {
            float4 a4 = *(const float4*)(Xt + k*68 + 4*ty);
            float4 b4 = *(const float4*)(Wt + k*68 + 4*tx);
            float a[4] = {a4.x, a4.y, a4.z, a4.w};
            float b[4] = {b4.x, b4.y, b4.z, b4.w};
            #pragma unroll
            for (int i = 0; i < 4; i++)
                #pragma unroll
                for (int j = 0; j < 4; j++)
                    acc[i][j] = fmaf(a[i], b[j], acc[i][j]);
        }
    }

    float4 bv4 = *(const float4*)(bias + n0 + 4*tx);
    #pragma unroll
    for (int i = 0; i < 4; i++) {
        __nv_bfloat162 p0 = __floats2bfloat162_rn(acc[i][0] + bv4.x, acc[i][1] + bv4.y);
        __nv_bfloat162 p1 = __floats2bfloat162_rn(acc[i][2] + bv4.z, acc[i][3] + bv4.w);
        uint2 pk;
        pk.x = *(uint32_t*)&p0;
        pk.y = *(uint32_t*)&p1;
        *(uint2*)(Y + (m0 + 4*ty + i)*EDIM + n0 + 4*tx) = pk;
    }
}

// ---------------------------------------------------------------------------
// bf16 flash attention, FA2-style register softmax + fused residual/LayerNorm.
// CTA: 128 queries, 16 warps (512 threads), key tiles of 64, 64 tiles/batch.
//
// Smem layout (bytes):
//   Qs bf16 [128][264] @0       (67584)
//   Ks bf16 [64][264]  @67584   (33792)
//   Vs bf16 [64][264]  @101376  (33792)
//   Ps bf16 [128][72]  @135168  (18432)
//   state f32          @153600  (3584): rm[128] rl[128] ra[128] sMax[2][128] sSum[2][128]
// Total 157184. Epilogue reuses [0,135168) as f32 staging [128][264].
// ---------------------------------------------------------------------------
#define SM_Q 0
#define QS_STR 264
#define SM_K 67584
#define KS_STR 264
#define SM_V 101376
#define VS_STR 264
#define SM_P 135168
#define PS_STR 72
#define SM_ST 153600
#define SM_BYTES 157184
#define VF_STR 264

__global__ __launch_bounds__(512, 1) void flash_kernel(
    const float* __restrict__ RES,
    const float* __restrict__ gamma, const float* __restrict__ beta,
    float* __restrict__ OUT)
{
    extern __shared__ char smem[];
    const uint32_t sb = smem_u32(smem);

    __nv_bfloat16* Qs = (__nv_bfloat16*)(smem + SM_Q);
    __nv_bfloat16* Ks = (__nv_bfloat16*)(smem + SM_K);
    __nv_bfloat16* Vs = (__nv_bfloat16*)(smem + SM_V);
    __nv_bfloat16* Ps = (__nv_bfloat16*)(smem + SM_P);
    float* rm   = (float*)(smem + SM_ST);
    float* rl   = rm + 128;
    float* ra   = rl + 128;
    float* sMax = ra + 128;     // [2][128]
    float* sSum = sMax + 256;   // [2][128]

    const int tid  = threadIdx.x;
    const int warp = tid >> 5;
    const int lane = tid & 31;
    const int ly   = lane >> 2;
    const int lx   = lane & 3;

    const int q0   = blockIdx.x << 7;
    const int base = blockIdx.y * SEQ * EDIM;
    const __nv_bfloat16* Qb = g_Q + base;
    const __nv_bfloat16* Kb = g_K + base;
    const __nv_bfloat16* Vb = g_V + base;

    // Phase-A (warps 0-7): 32 rows x 32 keys per warp
    const int rw = warp & 3;           // row group (also Phase C)
    const int kw = (warp >> 2) & 1;    // key half (Phase A)
    // Phase-C (all 16 warps): 32 rows x 64 dims per warp
    const int dw = warp >> 2;          // dim group 0..3

    // ldmatrix lane addressing
    const int a_row = lane & 15;
    const int a_k8  = (lane >> 4) << 3;
    const int b_n   = ((lane >> 4) << 3) + (lane & 7);
    const int b_k8  = ((lane >> 3) & 1) << 3;
    const int v_key = (((lane >> 3) & 1) << 3) + (lane & 7);
    const int v_d8  = (lane >> 4) << 3;

    // ---- Q fill [128 x 256] ----
    #pragma unroll
    for (int i = 0; i < 8; i++) {
        int idx = tid + i*512;
        int row = idx >> 5;
        int c8  = (idx & 31) << 3;
        *(uint4*)(Qs + row*QS_STR + c8) = *(const uint4*)(Qb + (q0 + row)*EDIM + c8);
    }
    if (tid < 128) { rm[tid] = -1e30f; rl[tid] = 0.0f; }

    float acc[2][8][4];
    #pragma unroll
    for (int mt = 0; mt < 2; mt++)
        #pragma unroll
        for (int nb = 0; nb < 8; nb++)
            #pragma unroll
            for (int r = 0; r < 4; r++) acc[mt][nb][r] = 0.0f;

    for (int kt = 0; kt < 64; kt++) {        // 64 tiles x 64 keys = SEQ=4096
        const int key0 = kt << 6;
        __syncthreads();   // prior Phase C done: K/V/P buffers free

        if (warp < 8) {
            // ---- fill K [64 x 256] (threads 0-255) ----
            #pragma unroll
            for (int i = 0; i < 8; i++) {
                int idx = tid + i*256;
                int row = idx >> 5;
                int c8  = (idx & 31) << 3;
                *(uint4*)(Ks + row*KS_STR + c8) =
                    *(const uint4*)(Kb + (key0 + row)*EDIM + c8);
            }
            BAR1_SYNC();   // K ready for Phase A warps

            // ---- Phase A: S[32 rows x 32 keys] per warp ----
            float sC[2][4][4];
            #pragma unroll
            for (int mt = 0; mt < 2; mt++)
                #pragma unroll
                for (int nb = 0; nb < 4; nb++)
                    #pragma unroll
                    for (int r = 0; r < 4; r++) sC[mt][nb][r] = 0.0f;

            #pragma unroll
            for (int kb = 0; kb < 16; kb++) {
                uint32_t a[2][4];
                #pragma unroll
                for (int mt = 0; mt < 2; mt++)
                    ldsm_x4(a[mt][0], a[mt][1], a[mt][2], a[mt][3],
                            sb + SM_Q + (((rw<<5) + (mt<<4) + a_row)*QS_STR + (kb<<4) + a_k8)*2);
                #pragma unroll
                for (int h = 0; h < 2; h++) {
                    uint32_t b0, b1, b2, b3;
                    ldsm_x4(b0, b1, b2, b3,
                            sb + SM_K + (((kw<<5) + (h<<4) + b_n)*KS_STR + (kb<<4) + b_k8)*2);
                    #pragma unroll
                    for (int mt = 0; mt < 2; mt++) {
                        mma_bf16(sC[mt][2*h    ], a[mt][0], a[mt][1], a[mt][2], a[mt][3], b0, b1);
                        mma_bf16(sC[mt][2*h + 1], a[mt][0], a[mt][1], a[mt][2], a[mt][3], b2, b3);
                    }
                }
            }

            // scale (1/sqrt(4096))
            #pragma unroll
            for (int mt = 0; mt < 2; mt++)
                #pragma unroll
                for (int nb = 0; nb < 4; nb++)
                    #pragma unroll
                    for (int r = 0; r < 4; r++) sC[mt][nb][r] *= 0.015625f;

            // ---- register softmax: per-warp partial row max ----
            float pmx[2][2];
            #pragma unroll
            for (int mt = 0; mt < 2; mt++) {
                float m0 = sC[mt][0][0], m1 = sC[mt][0][2];
                #pragma unroll
                for (int nb = 0; nb < 4; nb++) {
                    m0 = fmaxf(m0, fmaxf(sC[mt][nb][0], sC[mt][nb][1]));
                    m1 = fmaxf(m1, fmaxf(sC[mt][nb][2], sC[mt][nb][3]));
                }
                m0 = fmaxf(m0, __shfl_xor_sync(0xffffffffu, m0, 1));
                m0 = fmaxf(m0, __shfl_xor_sync(0xffffffffu, m0, 2));
                m1 = fmaxf(m1, __shfl_xor_sync(0xffffffffu, m1, 1));
                m1 = fmaxf(m1, __shfl_xor_sync(0xffffffffu, m1, 2));
                pmx[mt][0] = m0; pmx[mt][1] = m1;
            }
            if (lx == 0) {
                #pragma unroll
                for (int mt = 0; mt < 2; mt++) {
                    sMax[kw*128 + (rw<<5) + (mt<<4) + ly    ] = pmx[mt][0];
                    sMax[kw*128 + (rw<<5) + (mt<<4) + ly + 8] = pmx[mt][1];
                }
            }
            BAR1_SYNC();

            // combine maxes, exp, partial sums, write P (bf16)
            float mxn[2][2], mo[2][2];
            #pragma unroll
            for (int mt = 0; mt < 2; mt++) {
                int r0 = (rw<<5) + (mt<<4) + ly;
                mo[mt][0] = rm[r0];     mo[mt][1] = rm[r0 + 8];
                mxn[mt][0] = fmaxf(fmaxf(sMax[r0],     sMax[128 + r0]),     mo[mt][0]);
                mxn[mt][1] = fmaxf(fmaxf(sMax[r0 + 8], sMax[128 + r0 + 8]), mo[mt][1]);
            }
            float ps[2][2] = {};
            #pragma unroll
            for (int mt = 0; mt < 2; mt++) {
                int r0 = (rw<<5) + (mt<<4) + ly;
                #pragma unroll
                for (int nb = 0; nb < 4; nb++) {
                    float e0 = __expf(sC[mt][nb][0] - mxn[mt][0]);
                    float e1 = __expf(sC[mt][nb][1] - mxn[mt][0]);
                    float e2 = __expf(sC[mt][nb][2] - mxn[mt][1]);
                    float e3 = __expf(sC[mt][nb][3] - mxn[mt][1]);
                    ps[mt][0] += e0 + e1;
                    ps[mt][1] += e2 + e3;
                    __nv_bfloat162 q01 = __floats2bfloat162_rn(e0, e1);
                    __nv_bfloat162 q23 = __floats2bfloat162_rn(e2, e3);
                    int col = (kw<<5) + (nb<<3) + (lx<<1);
                    *(uint32_t*)(Ps + r0*PS_STR + col)       = *(uint32_t*)&q01;
                    *(uint32_t*)(Ps + (r0 + 8)*PS_STR + col) = *(uint32_t*)&q23;
                }
                ps[mt][0] += __shfl_xor_sync(0xffffffffu, ps[mt][0], 1);
                ps[mt][0] += __shfl_xor_sync(0xffffffffu, ps[mt][0], 2);
                ps[mt][1] += __shfl_xor_sync(0xffffffffu, ps[mt][1], 1);
                ps[mt][1] += __shfl_xor_sync(0xffffffffu, ps[mt][1], 2);
            }
            if (lx == 0) {
                #pragma unroll
                for (int mt = 0; mt < 2; mt++) {
                    sSum[kw*128 + (rw<<5) + (mt<<4) + ly    ] = ps[mt][0];
                    sSum[kw*128 + (rw<<5) + (mt<<4) + ly + 8] = ps[mt][1];
                }
            }
            BAR1_SYNC();

            if (kw == 0 && lx == 0) {
                #pragma unroll
                for (int mt = 0; mt < 2; mt++)
                    #pragma unroll
                    for (int hh = 0; hh < 2; hh++) {
                        int row = (rw<<5) + (mt<<4) + ly + hh*8;
                        float alpha = __expf(mo[mt][hh] - mxn[mt][hh]);
                        rl[row] = rl[row]*alpha + sSum[row] + sSum[128 + row];
                        ra[row] = alpha;
                        rm[row] = mxn[mt][hh];
                    }
            }
        } else {
            // ---- fill V [64 x 256] (threads 256-511), hidden behind Phase A ----
            int t2 = tid - 256;
            #pragma unroll
            for (int i = 0; i < 8; i++) {
                int idx = t2 + i*256;
                int row = idx >> 5;
                int c8  = (idx & 31) << 3;
                *(uint4*)(Vs + row*VS_STR + c8) =
                    *(const uint4*)(Vb + (key0 + row)*EDIM + c8);
            }
        }
        __syncthreads();   // P, ra, V ready

        // ---- Phase C: O[32 rows x 64 dims] += P . V (all 16 warps) ----
        float al[2][2];
        #pragma unroll
        for (int mt = 0; mt < 2; mt++) {
            al[mt][0] = ra[(rw<<5) + (mt<<4) + ly];
            al[mt][1] = ra[(rw<<5) + (mt<<4) + ly + 8];
        }
        #pragma unroll
        for (int mt = 0; mt < 2; mt++)
            #pragma unroll
            for (int nb = 0; nb < 8; nb++) {
                acc[mt][nb][0] *= al[mt][0]; acc[mt][nb][1] *= al[mt][0];
                acc[mt][nb][2] *= al[mt][1]; acc[mt][nb][3] *= al[mt][1];
            }

        #pragma unroll
        for (int kb = 0; kb < 4; kb++) {
            uint32_t a[2][4];
            #pragma unroll
            for (int mt = 0; mt < 2; mt++)
                ldsm_x4(a[mt][0], a[mt][1], a[mt][2], a[mt][3],
                        sb + SM_P + (((rw<<5) + (mt<<4) + a_row)*PS_STR + (kb<<4) + a_k8)*2);
            #pragma unroll
            for (int bp = 0; bp < 4; bp++) {
                uint32_t b0, b1, b2, b3;
                ldsm_x4t(b0, b1, b2, b3,
                         sb + SM_V + (((kb<<4) + v_key)*VS_STR + (dw<<6) + (bp<<4) + v_d8)*2);
                #pragma unroll
                for (int mt = 0; mt < 2; mt++) {
                    mma_bf16(acc[mt][2*bp    ], a[mt][0], a[mt][1], a[mt][2], a[mt][3], b0, b1);
                    mma_bf16(acc[mt][2*bp + 1], a[mt][0], a[mt][1], a[mt][2], a[mt][3], b2, b3);
                }
            }
        }
    }
    __syncthreads();

    // ---- Epilogue: scatter h = acc/rl into f32 staging, residual + LayerNorm ----
    float* Vf = (float*)smem;   // [128][VF_STR] f32, reuses Q/K/V space
    #pragma unroll
    for (int mt = 0; mt < 2; mt++) {
        int r0 = (rw<<5) + (mt<<4) + ly;
        float il0 = 1.0f / rl[r0];
        float il1 = 1.0f / rl[r0 + 8];
        #pragma unroll
        for (int nb = 0; nb < 8; nb++) {
            int col = (dw<<6) + (nb<<3) + (lx<<1);
            *(float2*)(Vf + r0*VF_STR + col) =
                make_float2(acc[mt][nb][0]*il0, acc[mt][nb][1]*il0);
            *(float2*)(Vf + (r0 + 8)*VF_STR + col) =
                make_float2(acc[mt][nb][2]*il1, acc[mt][nb][3]*il1);
        }
    }
    __syncthreads();

    #pragma unroll
    for (int rr = 0; rr < 8; rr++) {
        const int row = (warp << 3) + rr;
        const int d   = lane << 3;
        float4 h0 = *(float4*)(Vf + row*VF_STR + d);
        float4 h1 = *(float4*)(Vf + row*VF_STR + d + 4);
        const float* resrow = RES + base + (q0 + row)*EDIM + d;
        float4 x0 = *(const float4*)(resrow);
        float4 x1 = *(const float4*)(resrow + 4);
        h0.x += x0.x; h0.y += x0.y; h0.z += x0.z; h0.w += x0.w;
        h1.x += x1.x; h1.y += x1.y; h1.z += x1.z; h1.w += x1.w;
        float s1 = h0.x+h0.y+h0.z+h0.w + h1.x+h1.y+h1.z+h1.w;
        float s2 = h0.x*h0.x + h0.y*h0.y + h0.z*h0.z + h0.w*h0.w
                 + h1.x*h1.x + h1.y*h1.y + h1.z*h1.z + h1.w*h1.w;
        #pragma unroll
        for (int off = 16; off >= 1; off >>= 1) {
            s1 += __shfl_xor_sync(0xffffffffu, s1, off);
            s2 += __shfl_xor_sync(0xffffffffu, s2, off);
        }
        const float mu  = s1 * (1.0f/256.0f);
        const float var = s2 * (1.0f/256.0f) - mu*mu;
        const float rs  = rsqrtf(var + 1e-5f);
        float4 g0 = *(const float4*)(gamma + d);
        float4 g1 = *(const float4*)(gamma + d + 4);
        float4 b0 = *(const float4*)(beta + d);
        float4 b1 = *(const float4*)(beta + d + 4);
        float4 o0, o1;
        o0.x = (h0.x-mu)*rs*g0.x + b0.x;  o0.y = (h0.y-mu)*rs*g0.y + b0.y;
        o0.z = (h0.z-mu)*rs*g0.z + b0.z;  o0.w = (h0.w-mu)*rs*g0.w + b0.w;
        o1.x = (h1.x-mu)*rs*g1.x + b1.x;  o1.y = (h1.y-mu)*rs*g1.y + b1.y;
        o1.z = (h1.z-mu)*rs*g1.z + b1.z;  o1.w = (h1.w-mu)*rs*g1.w + b1.w;
        float* orow = OUT + base + (q0 + row)*EDIM + d;
        *(float4*)(orow)     = o0;
        *(float4*)(orow + 4) = o1;
    }
}

// ---------------------------------------------------------------------------
extern "C" void kernel_launch(void* const* d_in, const int* in_sizes, int n_in,
                              void* d_out, int out_size) {
    const float* x     = (const float*)d_in[0];
    const float* Wq1   = (const float*)d_in[1];
    const float* bq1   = (const float*)d_in[2];
    const float* Wk1   = (const float*)d_in[3];
    const float* bk1   = (const float*)d_in[4];
    const float* Wv1   = (const float*)d_in[5];
    const float* bv1   = (const float*)d_in[6];
    const float* Wq2   = (const float*)d_in[7];
    const float* bq2   = (const float*)d_in[8];
    const float* Wk2   = (const float*)d_in[9];
    const float* bk2   = (const float*)d_in[10];
    const float* Wv2   = (const float*)d_in[11];
    const float* bv2   = (const float*)d_in[12];
    const float* g1    = (const float*)d_in[13];
    const float* beta1 = (const float*)d_in[14];
    const float* g2    = (const float*)d_in[15];
    const float* beta2 = (const float*)d_in[16];
    float* out = (float*)d_out;

    float* O = nullptr;
    cudaGetSymbolAddress((void**)&O, g_O);

    cudaFuncSetAttribute(flash_kernel, cudaFuncAttributeMaxDynamicSharedMemorySize, SM_BYTES);

    dim3 pg(NTOK/64, 12), pb(256);
    dim3 fg(SEQ/128, BATCH), fb(512);

    // Layer 1
    proj_kernel<<<pg, pb>>>(x, Wq1, bq1, Wk1, bk1, Wv1, bv1);
    flash_kernel<<<fg, fb, SM_BYTES>>>(x, g1, beta1, O);
    // Layer 2
    proj_kernel<<<pg, pb>>>(O, Wq2, bq2, Wk2, bk2, Wv2, bv2);
    flash_kernel<<<fg, fb, SM_BYTES>>>(O, g2, beta2, out);
}

// round 15
// speedup vs baseline: 4.1397x; 1.5147x over previous
#include <cuda_runtime.h>
#include <cuda_bf16.h>
#include <cstdint>

#define BATCH 4
#define SEQ   4096
#define EDIM  256
#define NTOK  (BATCH*SEQ)

// Scratch (device globals: no allocation allowed in kernel_launch)
__device__ __nv_bfloat16 g_Q[NTOK*EDIM];
__device__ __nv_bfloat16 g_K[NTOK*EDIM];
__device__ __nv_bfloat16 g_V[NTOK*EDIM];
__device__ float         g_O[NTOK*EDIM];

// ---------------------------------------------------------------------------
// mma / ldmatrix helpers (bf16 m16n8k16, fp32 accum)
// ---------------------------------------------------------------------------
__device__ __forceinline__ uint32_t smem_u32(const void* p) {
    uint32_t a;
    asm("{ .reg .u64 t; cvta.to.shared.u64 t, %1; cvt.u32.u64 %0, t; }" : "=r"(a) : "l"(p));
    return a;
}

__device__ __forceinline__ void mma_bf16(float* c,
                                         uint32_t a0, uint32_t a1, uint32_t a2, uint32_t a3,
                                         uint32_t b0, uint32_t b1) {
    asm volatile(
        "mma.sync.aligned.m16n8k16.row.col.f32.bf16.bf16.f32 "
        "{%0,%1,%2,%3}, {%4,%5,%6,%7}, {%8,%9}, {%0,%1,%2,%3};"
        : "+f"(c[0]), "+f"(c[1]), "+f"(c[2]), "+f"(c[3])
        : "r"(a0), "r"(a1), "r"(a2), "r"(a3), "r"(b0), "r"(b1));
}

__device__ __forceinline__ void ldsm_x4(uint32_t& r0, uint32_t& r1, uint32_t& r2, uint32_t& r3,
                                        uint32_t addr) {
    asm volatile("ldmatrix.sync.aligned.m8n8.x4.shared.b16 {%0,%1,%2,%3}, [%4];"
                 : "=r"(r0), "=r"(r1), "=r"(r2), "=r"(r3) : "r"(addr));
}

__device__ __forceinline__ void ldsm_x4t(uint32_t& r0, uint32_t& r1, uint32_t& r2, uint32_t& r3,
                                         uint32_t addr) {
    asm volatile("ldmatrix.sync.aligned.m8n8.x4.trans.shared.b16 {%0,%1,%2,%3}, [%4];"
                 : "=r"(r0), "=r"(r1), "=r"(r2), "=r"(r3) : "r"(addr));
}

#define BAR1_SYNC() asm volatile("bar.sync 1, 256;" ::: "memory")

// ---------------------------------------------------------------------------
// Tensor-core QKV projection: Y[m,n] = bf16( sum_k X[m,k]*W[n,k] + b[n] )
// CTA: 128 rows x 128 cols, 8 warps (4 row-groups x 2 col-groups),
// K chunked by 64 (4 chunks). X/W converted fp32->bf16 on smem fill.
// grid = (NTOK/128, 6): blockIdx.y -> {Wq,Wk,Wv} x {col half 0,1}.
// ---------------------------------------------------------------------------
#define PJ_STR 72   // bf16 units; 36 words == 4 mod 32 -> ldsm conflict-free

__global__ __launch_bounds__(256) void proj_mma_kernel(
    const float* __restrict__ X,
    const float* __restrict__ Wq, const float* __restrict__ bq,
    const float* __restrict__ Wk, const float* __restrict__ bk,
    const float* __restrict__ Wv, const float* __restrict__ bv)
{
    __shared__ __align__(16) __nv_bfloat16 Xs[128*PJ_STR];
    __shared__ __align__(16) __nv_bfloat16 Ws[128*PJ_STR];
    const uint32_t xs_b = smem_u32(Xs);
    const uint32_t ws_b = smem_u32(Ws);

    const int m0    = blockIdx.x << 7;
    const int which = blockIdx.y >> 1;          // 0=q 1=k 2=v
    const int nbase = (blockIdx.y & 1) << 7;    // col half within the weight

    const float* W    = (which == 0) ? Wq : (which == 1) ? Wk : Wv;
    const float* bias = (which == 0) ? bq : (which == 1) ? bk : bv;
    __nv_bfloat16* Y  = (which == 0) ? g_Q : (which == 1) ? g_K : g_V;

    const int tid  = threadIdx.x;
    const int warp = tid >> 5;
    const int lane = tid & 31;
    const int ly   = lane >> 2;
    const int lx   = lane & 3;

    const int rw = warp & 3;    // row group: 32 rows
    const int cw = warp >> 2;   // col group: 64 cols

    // ldmatrix lane addressing (same pattern as flash Phase A)
    const int a_row = lane & 15;
    const int a_k8  = (lane >> 4) << 3;
    const int b_n   = ((lane >> 4) << 3) + (lane & 7);
    const int b_k8  = ((lane >> 3) & 1) << 3;

    float acc[2][8][4];
    #pragma unroll
    for (int mt = 0; mt < 2; mt++)
        #pragma unroll
        for (int nb = 0; nb < 8; nb++)
            #pragma unroll
            for (int r = 0; r < 4; r++) acc[mt][nb][r] = 0.0f;

    for (int kc = 0; kc < 4; kc++) {
        __syncthreads();
        // fill X chunk [128 rows x 64 k] and W chunk [128 n x 64 k], fp32->bf16
        #pragma unroll
        for (int i = 0; i < 8; i++) {
            int idx = tid + i*256;          // float4 slots: 128*16
            int row = idx >> 4;
            int c4  = (idx & 15) << 2;
            float4 xv = *(const float4*)(X + (m0 + row)*EDIM + (kc<<6) + c4);
            __nv_bfloat162 h0 = __floats2bfloat162_rn(xv.x, xv.y);
            __nv_bfloat162 h1 = __floats2bfloat162_rn(xv.z, xv.w);
            uint2 pk; pk.x = *(uint32_t*)&h0; pk.y = *(uint32_t*)&h1;
            *(uint2*)(Xs + row*PJ_STR + c4) = pk;

            float4 wv = *(const float4*)(W + (nbase + row)*EDIM + (kc<<6) + c4);
            __nv_bfloat162 g0 = __floats2bfloat162_rn(wv.x, wv.y);
            __nv_bfloat162 g1 = __floats2bfloat162_rn(wv.z, wv.w);
            uint2 qk; qk.x = *(uint32_t*)&g0; qk.y = *(uint32_t*)&g1;
            *(uint2*)(Ws + row*PJ_STR + c4) = qk;
        }
        __syncthreads();

        #pragma unroll
        for (int kb = 0; kb < 4; kb++) {
            uint32_t a[2][4];
            #pragma unroll
            for (int mt = 0; mt < 2; mt++)
                ldsm_x4(a[mt][0], a[mt][1], a[mt][2], a[mt][3],
                        xs_b + (((rw<<5) + (mt<<4) + a_row)*PJ_STR + (kb<<4) + a_k8)*2);
            #pragma unroll
            for (int h = 0; h < 4; h++) {
                uint32_t b0, b1, b2, b3;
                ldsm_x4(b0, b1, b2, b3,
                        ws_b + (((cw<<6) + (h<<4) + b_n)*PJ_STR + (kb<<4) + b_k8)*2);
                #pragma unroll
                for (int mt = 0; mt < 2; mt++) {
                    mma_bf16(acc[mt][2*h    ], a[mt][0], a[mt][1], a[mt][2], a[mt][3], b0, b1);
                    mma_bf16(acc[mt][2*h + 1], a[mt][0], a[mt][1], a[mt][2], a[mt][3], b2, b3);
                }
            }
        }
    }

    // epilogue: + bias, convert to bf16, store
    #pragma unroll
    for (int nb = 0; nb < 8; nb++) {
        const int col = nbase + (cw<<6) + (nb<<3) + (lx<<1);
        const float bc0 = bias[col];
        const float bc1 = bias[col + 1];
        #pragma unroll
        for (int mt = 0; mt < 2; mt++) {
            const int row = m0 + (rw<<5) + (mt<<4) + ly;
            __nv_bfloat162 o0 = __floats2bfloat162_rn(acc[mt][nb][0] + bc0,
                                                      acc[mt][nb][1] + bc1);
            __nv_bfloat162 o1 = __floats2bfloat162_rn(acc[mt][nb][2] + bc0,
                                                      acc[mt][nb][3] + bc1);
            *(uint32_t*)(Y + row*EDIM + col)       = *(uint32_t*)&o0;
            *(uint32_t*)(Y + (row + 8)*EDIM + col) = *(uint32_t*)&o1;
        }
    }
}

// ---------------------------------------------------------------------------
// bf16 flash attention (unchanged from R14 winner).
// CTA: 128 queries, 16 warps (512 threads), key tiles of 64, 64 tiles/batch.
// ---------------------------------------------------------------------------
#define SM_Q 0
#define QS_STR 264
#define SM_K 67584
#define KS_STR 264
#define SM_V 101376
#define VS_STR 264
#define SM_P 135168
#define PS_STR 72
#define SM_ST 153600
#define SM_BYTES 157184
#define VF_STR 264

__global__ __launch_bounds__(512, 1) void flash_kernel(
    const float* __restrict__ RES,
    const float* __restrict__ gamma, const float* __restrict__ beta,
    float* __restrict__ OUT)
{
    extern __shared__ char smem[];
    const uint32_t sb = smem_u32(smem);

    __nv_bfloat16* Qs = (__nv_bfloat16*)(smem + SM_Q);
    __nv_bfloat16* Ks = (__nv_bfloat16*)(smem + SM_K);
    __nv_bfloat16* Vs = (__nv_bfloat16*)(smem + SM_V);
    __nv_bfloat16* Ps = (__nv_bfloat16*)(smem + SM_P);
    float* rm   = (float*)(smem + SM_ST);
    float* rl   = rm + 128;
    float* ra   = rl + 128;
    float* sMax = ra + 128;     // [2][128]
    float* sSum = sMax + 256;   // [2][128]

    const int tid  = threadIdx.x;
    const int warp = tid >> 5;
    const int lane = tid & 31;
    const int ly   = lane >> 2;
    const int lx   = lane & 3;

    const int q0   = blockIdx.x << 7;
    const int base = blockIdx.y * SEQ * EDIM;
    const __nv_bfloat16* Qb = g_Q + base;
    const __nv_bfloat16* Kb = g_K + base;
    const __nv_bfloat16* Vb = g_V + base;

    const int rw = warp & 3;
    const int kw = (warp >> 2) & 1;
    const int dw = warp >> 2;

    const int a_row = lane & 15;
    const int a_k8  = (lane >> 4) << 3;
    const int b_n   = ((lane >> 4) << 3) + (lane & 7);
    const int b_k8  = ((lane >> 3) & 1) << 3;
    const int v_key = (((lane >> 3) & 1) << 3) + (lane & 7);
    const int v_d8  = (lane >> 4) << 3;

    #pragma unroll
    for (int i = 0; i < 8; i++) {
        int idx = tid + i*512;
        int row = idx >> 5;
        int c8  = (idx & 31) << 3;
        *(uint4*)(Qs + row*QS_STR + c8) = *(const uint4*)(Qb + (q0 + row)*EDIM + c8);
    }
    if (tid < 128) { rm[tid] = -1e30f; rl[tid] = 0.0f; }

    float acc[2][8][4];
    #pragma unroll
    for (int mt = 0; mt < 2; mt++)
        #pragma unroll
        for (int nb = 0; nb < 8; nb++)
            #pragma unroll
            for (int r = 0; r < 4; r++) acc[mt][nb][r] = 0.0f;

    for (int kt = 0; kt < 64; kt++) {
        const int key0 = kt << 6;
        __syncthreads();

        if (warp < 8) {
            #pragma unroll
            for (int i = 0; i < 8; i++) {
                int idx = tid + i*256;
                int row = idx >> 5;
                int c8  = (idx & 31) << 3;
                *(uint4*)(Ks + row*KS_STR + c8) =
                    *(const uint4*)(Kb + (key0 + row)*EDIM + c8);
            }
            BAR1_SYNC();

            float sC[2][4][4];
            #pragma unroll
            for (int mt = 0; mt < 2; mt++)
                #pragma unroll
                for (int nb = 0; nb < 4; nb++)
                    #pragma unroll
                    for (int r = 0; r < 4; r++) sC[mt][nb][r] = 0.0f;

            #pragma unroll
            for (int kb = 0; kb < 16; kb++) {
                uint32_t a[2][4];
                #pragma unroll
                for (int mt = 0; mt < 2; mt++)
                    ldsm_x4(a[mt][0], a[mt][1], a[mt][2], a[mt][3],
                            sb + SM_Q + (((rw<<5) + (mt<<4) + a_row)*QS_STR + (kb<<4) + a_k8)*2);
                #pragma unroll
                for (int h = 0; h < 2; h++) {
                    uint32_t b0, b1, b2, b3;
                    ldsm_x4(b0, b1, b2, b3,
                            sb + SM_K + (((kw<<5) + (h<<4) + b_n)*KS_STR + (kb<<4) + b_k8)*2);
                    #pragma unroll
                    for (int mt = 0; mt < 2; mt++) {
                        mma_bf16(sC[mt][2*h    ], a[mt][0], a[mt][1], a[mt][2], a[mt][3], b0, b1);
                        mma_bf16(sC[mt][2*h + 1], a[mt][0], a[mt][1], a[mt][2], a[mt][3], b2, b3);
                    }
                }
            }

            #pragma unroll
            for (int mt = 0; mt < 2; mt++)
                #pragma unroll
                for (int nb = 0; nb < 4; nb++)
                    #pragma unroll
                    for (int r = 0; r < 4; r++) sC[mt][nb][r] *= 0.015625f;

            float pmx[2][2];
            #pragma unroll
            for (int mt = 0; mt < 2; mt++) {
                float m0 = sC[mt][0][0], m1 = sC[mt][0][2];
                #pragma unroll
                for (int nb = 0; nb < 4; nb++) {
                    m0 = fmaxf(m0, fmaxf(sC[mt][nb][0], sC[mt][nb][1]));
                    m1 = fmaxf(m1, fmaxf(sC[mt][nb][2], sC[mt][nb][3]));
                }
                m0 = fmaxf(m0, __shfl_xor_sync(0xffffffffu, m0, 1));
                m0 = fmaxf(m0, __shfl_xor_sync(0xffffffffu, m0, 2));
                m1 = fmaxf(m1, __shfl_xor_sync(0xffffffffu, m1, 1));
                m1 = fmaxf(m1, __shfl_xor_sync(0xffffffffu, m1, 2));
                pmx[mt][0] = m0; pmx[mt][1] = m1;
            }
            if (lx == 0) {
                #pragma unroll
                for (int mt = 0; mt < 2; mt++) {
                    sMax[kw*128 + (rw<<5) + (mt<<4) + ly    ] = pmx[mt][0];
                    sMax[kw*128 + (rw<<5) + (mt<<4) + ly + 8] = pmx[mt][1];
                }
            }
            BAR1_SYNC();

            float mxn[2][2], mo[2][2];
            #pragma unroll
            for (int mt = 0; mt < 2; mt++) {
                int r0 = (rw<<5) + (mt<<4) + ly;
                mo[mt][0] = rm[r0];     mo[mt][1] = rm[r0 + 8];
                mxn[mt][0] = fmaxf(fmaxf(sMax[r0],     sMax[128 + r0]),     mo[mt][0]);
                mxn[mt][1] = fmaxf(fmaxf(sMax[r0 + 8], sMax[128 + r0 + 8]), mo[mt][1]);
            }
            float ps[2][2] = {};
            #pragma unroll
            for (int mt = 0; mt < 2; mt++) {
                int r0 = (rw<<5) + (mt<<4) + ly;
                #pragma unroll
                for (int nb = 0; nb < 4; nb++) {
                    float e0 = __expf(sC[mt][nb][0] - mxn[mt][0]);
                    float e1 = __expf(sC[mt][nb][1] - mxn[mt][0]);
                    float e2 = __expf(sC[mt][nb][2] - mxn[mt][1]);
                    float e3 = __expf(sC[mt][nb][3] - mxn[mt][1]);
                    ps[mt][0] += e0 + e1;
                    ps[mt][1] += e2 + e3;
                    __nv_bfloat162 q01 = __floats2bfloat162_rn(e0, e1);
                    __nv_bfloat162 q23 = __floats2bfloat162_rn(e2, e3);
                    int col = (kw<<5) + (nb<<3) + (lx<<1);
                    *(uint32_t*)(Ps + r0*PS_STR + col)       = *(uint32_t*)&q01;
                    *(uint32_t*)(Ps + (r0 + 8)*PS_STR + col) = *(uint32_t*)&q23;
                }
                ps[mt][0] += __shfl_xor_sync(0xffffffffu, ps[mt][0], 1);
                ps[mt][0] += __shfl_xor_sync(0xffffffffu, ps[mt][0], 2);
                ps[mt][1] += __shfl_xor_sync(0xffffffffu, ps[mt][1], 1);
                ps[mt][1] += __shfl_xor_sync(0xffffffffu, ps[mt][1], 2);
            }
            if (lx == 0) {
                #pragma unroll
                for (int mt = 0; mt < 2; mt++) {
                    sSum[kw*128 + (rw<<5) + (mt<<4) + ly    ] = ps[mt][0];
                    sSum[kw*128 + (rw<<5) + (mt<<4) + ly + 8] = ps[mt][1];
                }
            }
            BAR1_SYNC();

            if (kw == 0 && lx == 0) {
                #pragma unroll
                for (int mt = 0; mt < 2; mt++)
                    #pragma unroll
                    for (int hh = 0; hh < 2; hh++) {
                        int row = (rw<<5) + (mt<<4) + ly + hh*8;
                        float alpha = __expf(mo[mt][hh] - mxn[mt][hh]);
                        rl[row] = rl[row]*alpha + sSum[row] + sSum[128 + row];
                        ra[row] = alpha;
                        rm[row] = mxn[mt][hh];
                    }
            }
        } else {
            int t2 = tid - 256;
            #pragma unroll
            for (int i = 0; i < 8; i++) {
                int idx = t2 + i*256;
                int row = idx >> 5;
                int c8  = (idx & 31) << 3;
                *(uint4*)(Vs + row*VS_STR + c8) =
                    *(const uint4*)(Vb + (key0 + row)*EDIM + c8);
            }
        }
        __syncthreads();

        float al[2][2];
        #pragma unroll
        for (int mt = 0; mt < 2; mt++) {
            al[mt][0] = ra[(rw<<5) + (mt<<4) + ly];
            al[mt][1] = ra[(rw<<5) + (mt<<4) + ly + 8];
        }
        #pragma unroll
        for (int mt = 0; mt < 2; mt++)
            #pragma unroll
            for (int nb = 0; nb < 8; nb++) {
                acc[mt][nb][0] *= al[mt][0]; acc[mt][nb][1] *= al[mt][0];
                acc[mt][nb][2] *= al[mt][1]; acc[mt][nb][3] *= al[mt][1];
            }

        #pragma unroll
        for (int kb = 0; kb < 4; kb++) {
            uint32_t a[2][4];
            #pragma unroll
            for (int mt = 0; mt < 2; mt++)
                ldsm_x4(a[mt][0], a[mt][1], a[mt][2], a[mt][3],
                        sb + SM_P + (((rw<<5) + (mt<<4) + a_row)*PS_STR + (kb<<4) + a_k8)*2);
            #pragma unroll
            for (int bp = 0; bp < 4; bp++) {
                uint32_t b0, b1, b2, b3;
                ldsm_x4t(b0, b1, b2, b3,
                         sb + SM_V + (((kb<<4) + v_key)*VS_STR + (dw<<6) + (bp<<4) + v_d8)*2);
                #pragma unroll
                for (int mt = 0; mt < 2; mt++) {
                    mma_bf16(acc[mt][2*bp    ], a[mt][0], a[mt][1], a[mt][2], a[mt][3], b0, b1);
                    mma_bf16(acc[mt][2*bp + 1], a[mt][0], a[mt][1], a[mt][2], a[mt][3], b2, b3);
                }
            }
        }
    }
    __syncthreads();

    float* Vf = (float*)smem;
    #pragma unroll
    for (int mt = 0; mt < 2; mt++) {
        int r0 = (rw<<5) + (mt<<4) + ly;
        float il0 = 1.0f / rl[r0];
        float il1 = 1.0f / rl[r0 + 8];
        #pragma unroll
        for (int nb = 0; nb < 8; nb++) {
            int col = (dw<<6) + (nb<<3) + (lx<<1);
            *(float2*)(Vf + r0*VF_STR + col) =
                make_float2(acc[mt][nb][0]*il0, acc[mt][nb][1]*il0);
            *(float2*)(Vf + (r0 + 8)*VF_STR + col) =
                make_float2(acc[mt][nb][2]*il1, acc[mt][nb][3]*il1);
        }
    }
    __syncthreads();

    #pragma unroll
    for (int rr = 0; rr < 8; rr++) {
        const int row = (warp << 3) + rr;
        const int d   = lane << 3;
        float4 h0 = *(float4*)(Vf + row*VF_STR + d);
        float4 h1 = *(float4*)(Vf + row*VF_STR + d + 4);
        const float* resrow = RES + base + (q0 + row)*EDIM + d;
        float4 x0 = *(const float4*)(resrow);
        float4 x1 = *(const float4*)(resrow + 4);
        h0.x += x0.x; h0.y += x0.y; h0.z += x0.z; h0.w += x0.w;
        h1.x += x1.x; h1.y += x1.y; h1.z += x1.z; h1.w += x1.w;
        float s1 = h0.x+h0.y+h0.z+h0.w + h1.x+h1.y+h1.z+h1.w;
        float s2 = h0.x*h0.x + h0.y*h0.y + h0.z*h0.z + h0.w*h0.w
                 + h1.x*h1.x + h1.y*h1.y + h1.z*h1.z + h1.w*h1.w;
        #pragma unroll
        for (int off = 16; off >= 1; off >>= 1) {
            s1 += __shfl_xor_sync(0xffffffffu, s1, off);
            s2 += __shfl_xor_sync(0xffffffffu, s2, off);
        }
        const float mu  = s1 * (1.0f/256.0f);
        const float var = s2 * (1.0f/256.0f) - mu*mu;
        const float rs  = rsqrtf(var + 1e-5f);
        float4 g0 = *(const float4*)(gamma + d);
        float4 g1 = *(const float4*)(gamma + d + 4);
        float4 b0 = *(const float4*)(beta + d);
        float4 b1 = *(const float4*)(beta + d + 4);
        float4 o0, o1;
        o0.x = (h0.x-mu)*rs*g0.x + b0.x;  o0.y = (h0.y-mu)*rs*g0.y + b0.y;
        o0.z = (h0.z-mu)*rs*g0.z + b0.z;  o0.w = (h0.w-mu)*rs*g0.w + b0.w;
        o1.x = (h1.x-mu)*rs*g1.x + b1.x;  o1.y = (h1.y-mu)*rs*g1.y + b1.y;
        o1.z = (h1.z-mu)*rs*g1.z + b1.z;  o1.w = (h1.w-mu)*rs*g1.w + b1.w;
        float* orow = OUT + base + (q0 + row)*EDIM + d;
        *(float4*)(orow)     = o0;
        *(float4*)(orow + 4) = o1;
    }
}

// ---------------------------------------------------------------------------
extern "C" void kernel_launch(void* const* d_in, const int* in_sizes, int n_in,
                              void* d_out, int out_size) {
    const float* x     = (const float*)d_in[0];
    const float* Wq1   = (const float*)d_in[1];
    const float* bq1   = (const float*)d_in[2];
    const float* Wk1   = (const float*)d_in[3];
    const float* bk1   = (const float*)d_in[4];
    const float* Wv1   = (const float*)d_in[5];
    const float* bv1   = (const float*)d_in[6];
    const float* Wq2   = (const float*)d_in[7];
    const float* bq2   = (const float*)d_in[8];
    const float* Wk2   = (const float*)d_in[9];
    const float* bk2   = (const float*)d_in[10];
    const float* Wv2   = (const float*)d_in[11];
    const float* bv2   = (const float*)d_in[12];
    const float* g1    = (const float*)d_in[13];
    const float* beta1 = (const float*)d_in[14];
    const float* g2    = (const float*)d_in[15];
    const float* beta2 = (const float*)d_in[16];
    float* out = (float*)d_out;

    float* O = nullptr;
    cudaGetSymbolAddress((void**)&O, g_O);

    cudaFuncSetAttribute(flash_kernel, cudaFuncAttributeMaxDynamicSharedMemorySize, SM_BYTES);

    dim3 pg(NTOK/128, 6), pb(256);
    dim3 fg(SEQ/128, BATCH), fb(512);

    // Layer 1
    proj_mma_kernel<<<pg, pb>>>(x, Wq1, bq1, Wk1, bk1, Wv1, bv1);
    flash_kernel<<<fg, fb, SM_BYTES>>>(x, g1, beta1, O);
    // Layer 2
    proj_mma_kernel<<<pg, pb>>>(O, Wq2, bq2, Wk2, bk2, Wv2, bv2);
    flash_kernel<<<fg, fb, SM_BYTES>>>(O, g2, beta2, out);
}